// round 1
// baseline (speedup 1.0000x reference)
#include <cuda_runtime.h>
#include <math.h>

// Problem constants
#define BB 32
#define NN 1024
#define DD 768
#define E_TOKN 4
#define E_CHN 4
#define EE 8
#define TOPK 2
#define HNN 4096
#define HDD 3072
#define NPAIR (BB * TOPK)            // 64 selected (batch, expert) pairs
#define HID_ELEMS (DD * HNN)         // 3145728 == NN*HDD (same slot size for both expert types)
#define CON_ELEMS (NN * DD)          // 786432

// Static device scratch (no allocations allowed)
__device__ float g_xm[BB * DD];
__device__ int   g_pair_e[NPAIR];
__device__ float g_pair_w[NPAIR];
__device__ float g_hidden[NPAIR * HID_ELEMS];   // ~805 MB
__device__ float g_contrib[NPAIR * CON_ELEMS];  // ~201 MB

__device__ __forceinline__ float gelu_tanh(float v) {
    const float c = 0.7978845608028654f; // sqrt(2/pi)
    float u = c * (v + 0.044715f * v * v * v);
    return 0.5f * v * (1.0f + tanhf(u));
}

// ---------------------------------------------------------------------------
// Kernel 1: xm[b,d] = mean_n x[b,n,d]
// ---------------------------------------------------------------------------
__global__ void k_mean(const float* __restrict__ x) {
    int idx = blockIdx.x * blockDim.x + threadIdx.x;
    if (idx >= BB * DD) return;
    int b = idx / DD;
    int d = idx - b * DD;
    const float* p = x + (size_t)b * NN * DD + d;
    float s = 0.0f;
    #pragma unroll 8
    for (int n = 0; n < NN; n++) s += p[(size_t)n * DD];
    g_xm[idx] = s * (1.0f / (float)NN);
}

// ---------------------------------------------------------------------------
// Kernel 2: router logits, softmax, top-2, normalized weights, aux loss
// Single block, 256 threads (B*E = 256 logit dots).
// ---------------------------------------------------------------------------
__global__ void k_router(const float* __restrict__ rw, float* __restrict__ out,
                         long long aux_idx, int has_aux) {
    __shared__ float probs[BB][EE];   // logits first, then probs
    __shared__ int   top1s[BB];
    __shared__ float partial[EE];
    int t = threadIdx.x;

    // logits[b][e], one dot per thread (t = b*8 + e)
    {
        int b = t >> 3, e = t & 7;
        const float* xm = g_xm + b * DD;
        const float* w  = rw + e * DD;
        float s = 0.0f;
        #pragma unroll 8
        for (int d = 0; d < DD; d++) s += xm[d] * w[d];
        probs[b][e] = s;
    }
    __syncthreads();

    if (t < BB) {
        float l[EE];
        float mx = -1e30f;
        #pragma unroll
        for (int e = 0; e < EE; e++) { l[e] = probs[t][e]; mx = fmaxf(mx, l[e]); }
        float sum = 0.0f;
        #pragma unroll
        for (int e = 0; e < EE; e++) { l[e] = expf(l[e] - mx); sum += l[e]; }
        float inv = 1.0f / sum;
        #pragma unroll
        for (int e = 0; e < EE; e++) { l[e] *= inv; probs[t][e] = l[e]; }
        // top-2, lowest index wins ties (matches jax.lax.top_k)
        int i0 = 0; float v0 = l[0];
        #pragma unroll
        for (int e = 1; e < EE; e++) if (l[e] > v0) { v0 = l[e]; i0 = e; }
        int i1 = -1; float v1 = -1e30f;
        #pragma unroll
        for (int e = 0; e < EE; e++) if (e != i0 && l[e] > v1) { v1 = l[e]; i1 = e; }
        float inv01 = 1.0f / (v0 + v1);
        g_pair_e[2 * t]     = i0; g_pair_w[2 * t]     = v0 * inv01;
        g_pair_e[2 * t + 1] = i1; g_pair_w[2 * t + 1] = v1 * inv01;
        top1s[t] = i0;
    }
    __syncthreads();

    if (t < EE) {
        float ps = 0.0f; int c = 0;
        for (int b = 0; b < BB; b++) { ps += probs[b][t]; c += (top1s[b] == t); }
        partial[t] = ps * (float)c;
    }
    __syncthreads();

    if (t == 0 && has_aux) {
        float s = 0.0f;
        #pragma unroll
        for (int e = 0; e < EE; e++) s += partial[e];
        out[aux_idx] = s * ((float)EE / ((float)BB * (float)BB));
    }
}

// ---------------------------------------------------------------------------
// Generic fp32 tiled GEMM core: C[m][n'] = sum_k A[m][k] * B[n'][k] (+bias)(gelu)
//   ATRANS: A stored as (K x M), A[m][k] = Ap[k*M + m]   (else row-major M x K)
//   B always row-major (N' x K), K-contiguous.
//   BIAS: 0 none, 1 per-column (n'), 2 per-row (m)
// 128x128 tile, BK=16, 256 threads, 8x8 per thread.
// ---------------------------------------------------------------------------
template <int M, int Nn, int K, bool ATRANS, bool DOGELU, int BIAS>
__device__ __forceinline__ void gemm_core(const float* __restrict__ A,
                                          const float* __restrict__ Bm,
                                          const float* __restrict__ bias,
                                          float* __restrict__ C) {
    constexpr int BM = 128, BN = 128, BK = 16;
    constexpr int lda = ATRANS ? M : K;
    __shared__ __align__(16) float As[BK][BM];
    __shared__ __align__(16) float Bs[BK][BN];

    const int tid = threadIdx.x;
    const int tx = tid & 15;       // column group
    const int ty = tid >> 4;       // row group
    const int mTile = blockIdx.y * BM;
    const int nTile = blockIdx.x * BN;

    float acc[8][8];
    #pragma unroll
    for (int i = 0; i < 8; i++)
        #pragma unroll
        for (int j = 0; j < 8; j++) acc[i][j] = 0.0f;

    for (int k0 = 0; k0 < K; k0 += BK) {
        // --- load A tile into As[k][m] ---
        if (ATRANS) {
            #pragma unroll
            for (int i = 0; i < 8; i++) {
                int l = tid + i * 256;          // 0..2047
                int k = l >> 7, m = l & 127;
                As[k][m] = A[(size_t)(k0 + k) * lda + (mTile + m)];
            }
        } else {
            #pragma unroll
            for (int i = 0; i < 2; i++) {
                int l4 = tid + i * 256;         // 0..511
                int m = l4 >> 2, k4 = l4 & 3;
                float4 v = *(const float4*)(A + (size_t)(mTile + m) * lda + k0 + k4 * 4);
                As[k4 * 4 + 0][m] = v.x; As[k4 * 4 + 1][m] = v.y;
                As[k4 * 4 + 2][m] = v.z; As[k4 * 4 + 3][m] = v.w;
            }
        }
        // --- load B tile into Bs[k][n] ---
        #pragma unroll
        for (int i = 0; i < 2; i++) {
            int l4 = tid + i * 256;
            int n = l4 >> 2, k4 = l4 & 3;
            float4 v = *(const float4*)(Bm + (size_t)(nTile + n) * K + k0 + k4 * 4);
            Bs[k4 * 4 + 0][n] = v.x; Bs[k4 * 4 + 1][n] = v.y;
            Bs[k4 * 4 + 2][n] = v.z; Bs[k4 * 4 + 3][n] = v.w;
        }
        __syncthreads();

        #pragma unroll
        for (int k = 0; k < BK; k++) {
            float a[8], b[8];
            *(float4*)(a)     = *(const float4*)&As[k][ty * 8];
            *(float4*)(a + 4) = *(const float4*)&As[k][ty * 8 + 4];
            *(float4*)(b)     = *(const float4*)&Bs[k][tx * 8];
            *(float4*)(b + 4) = *(const float4*)&Bs[k][tx * 8 + 4];
            #pragma unroll
            for (int i = 0; i < 8; i++)
                #pragma unroll
                for (int j = 0; j < 8; j++) acc[i][j] += a[i] * b[j];
        }
        __syncthreads();
    }

    // --- epilogue ---
    #pragma unroll
    for (int i = 0; i < 8; i++) {
        int row = mTile + ty * 8 + i;
        float rb = (BIAS == 2) ? bias[row] : 0.0f;
        #pragma unroll
        for (int jj = 0; jj < 2; jj++) {
            float tmp[4];
            #pragma unroll
            for (int j4 = 0; j4 < 4; j4++) {
                int col = nTile + tx * 8 + jj * 4 + j4;
                float v = acc[i][jj * 4 + j4];
                if (BIAS == 1) v += bias[col];
                else if (BIAS == 2) v += rb;
                if (DOGELU) v = gelu_tanh(v);
                tmp[j4] = v;
            }
            *(float4*)(C + (size_t)row * Nn + nTile + tx * 8 + jj * 4) =
                make_float4(tmp[0], tmp[1], tmp[2], tmp[3]);
        }
    }
}

// ---------------------------------------------------------------------------
// Expert GEMM wrappers — one grid.z slot per (batch, top-k) pair,
// early exit on expert type (exact top-2 sparsity).
// ---------------------------------------------------------------------------
__global__ void __launch_bounds__(256)
k_tok_l1(const float* __restrict__ x, const float* __restrict__ w1,
         const float* __restrict__ b1) {
    int p = blockIdx.z;
    int e = g_pair_e[p];
    if (e >= E_TOKN) return;
    int b = p >> 1;
    // H[p][d][h] = gelu( sum_n x[b][n][d] * w1[e][h][n] + b1[e][h] )
    gemm_core<DD, HNN, NN, true, true, 1>(
        x + (size_t)b * NN * DD, w1 + (size_t)e * HNN * NN, b1 + e * HNN,
        g_hidden + (size_t)p * HID_ELEMS);
}

__global__ void __launch_bounds__(256)
k_tok_l2(const float* __restrict__ w2, const float* __restrict__ b2) {
    int p = blockIdx.z;
    int e = g_pair_e[p];
    if (e >= E_TOKN) return;
    // contrib[p][n][d] = sum_h w2[e][n][h] * H[p][d][h] + b2[e][n]
    gemm_core<NN, DD, HNN, false, false, 2>(
        w2 + (size_t)e * NN * HNN, g_hidden + (size_t)p * HID_ELEMS, b2 + e * NN,
        g_contrib + (size_t)p * CON_ELEMS);
}

__global__ void __launch_bounds__(256)
k_ch_l1(const float* __restrict__ x, const float* __restrict__ w1,
        const float* __restrict__ b1) {
    int p = blockIdx.z;
    int e = g_pair_e[p];
    if (e < E_TOKN) return;
    e -= E_TOKN;
    int b = p >> 1;
    // G[p][n][h] = gelu( sum_d x[b][n][d] * w1[e][h][d] + b1[e][h] )
    gemm_core<NN, HDD, DD, false, true, 1>(
        x + (size_t)b * NN * DD, w1 + (size_t)e * HDD * DD, b1 + e * HDD,
        g_hidden + (size_t)p * HID_ELEMS);
}

__global__ void __launch_bounds__(256)
k_ch_l2(const float* __restrict__ w2, const float* __restrict__ b2) {
    int p = blockIdx.z;
    int e = g_pair_e[p];
    if (e < E_TOKN) return;
    e -= E_TOKN;
    // contrib[p][n][d] = sum_h G[p][n][h] * w2[e][d][h] + b2[e][d]
    gemm_core<NN, DD, HDD, false, false, 1>(
        g_hidden + (size_t)p * HID_ELEMS, w2 + (size_t)e * DD * HDD, b2 + e * DD,
        g_contrib + (size_t)p * CON_ELEMS);
}

// ---------------------------------------------------------------------------
// Final combine: out[b,n,d] = w[2b]*contrib[2b] + w[2b+1]*contrib[2b+1]
// Writes every element (output buffer is poisoned, no zeroing needed).
// ---------------------------------------------------------------------------
__global__ void k_combine(float* __restrict__ out) {
    long long idx = (long long)blockIdx.x * 256 + threadIdx.x;
    if (idx >= (long long)BB * NN * DD) return;
    int b = (int)(idx / (NN * DD));
    int r = (int)(idx - (long long)b * (NN * DD));
    float v0 = g_pair_w[2 * b]     * g_contrib[(size_t)(2 * b) * CON_ELEMS + r];
    float v1 = g_pair_w[2 * b + 1] * g_contrib[(size_t)(2 * b + 1) * CON_ELEMS + r];
    out[idx] = v0 + v1;
}

// ---------------------------------------------------------------------------
// Launch
// ---------------------------------------------------------------------------
extern "C" void kernel_launch(void* const* d_in, const int* in_sizes, int n_in,
                              void* d_out, int out_size) {
    const float* x        = (const float*)d_in[0];
    const float* router_w = (const float*)d_in[1];
    const float* tok_w1   = (const float*)d_in[2];
    const float* tok_b1   = (const float*)d_in[3];
    const float* tok_w2   = (const float*)d_in[4];
    const float* tok_b2   = (const float*)d_in[5];
    const float* ch_w1    = (const float*)d_in[6];
    const float* ch_b1    = (const float*)d_in[7];
    const float* ch_w2    = (const float*)d_in[8];
    const float* ch_b2    = (const float*)d_in[9];
    float* out = (float*)d_out;

    long long bnd = (long long)BB * NN * DD;
    int has_aux = (long long)out_size > bnd;

    k_mean<<<(BB * DD + 255) / 256, 256>>>(x);
    k_router<<<1, 256>>>(router_w, out, bnd, has_aux);

    dim3 g_tok1(HNN / 128, DD / 128, NPAIR);   // 32 x 6 x 64
    k_tok_l1<<<g_tok1, 256>>>(x, tok_w1, tok_b1);

    dim3 g_ch1(HDD / 128, NN / 128, NPAIR);    // 24 x 8 x 64
    k_ch_l1<<<g_ch1, 256>>>(x, ch_w1, ch_b1);

    dim3 g_l2(DD / 128, NN / 128, NPAIR);      // 6 x 8 x 64
    k_tok_l2<<<g_l2, 256>>>(tok_w2, tok_b2);
    k_ch_l2<<<g_l2, 256>>>(ch_w2, ch_b2);

    long long tot = bnd;
    k_combine<<<(unsigned)((tot + 255) / 256), 256>>>(out);
}

// round 6
// speedup vs baseline: 1.5272x; 1.5272x over previous
#include <cuda_runtime.h>
#include <cuda_bf16.h>
#include <mma.h>
#include <math.h>
#include <stdint.h>

using namespace nvcuda;

// ---------------------------------------------------------------------------
// Problem constants
// ---------------------------------------------------------------------------
#define BB 32
#define NN 1024
#define DD 768
#define E_TOKN 4
#define E_CHN 4
#define EE 8
#define TOPK 2
#define HNN 4096
#define HDD 3072
#define NPAIR (BB * TOPK)            // 64 selected (batch, expert) pairs
#define HID_ELEMS (DD * HNN)         // 3145728 == NN*HDD
#define CON_ELEMS (NN * DD)          // 786432

// ---------------------------------------------------------------------------
// Static device scratch — uint4/float4-typed for guaranteed 16B alignment.
// RULE (root cause of rounds 3-5): device-global addresses must ONLY be
// formed in DEVICE code. Host code passing g_* as kernel args gets the host
// shadow symbol, which on GB300 (ATS) is silently GPU-writable -> data loss.
// ---------------------------------------------------------------------------
__device__ float g_xm[BB * DD];
__device__ int   g_pair_e[NPAIR];
__device__ float g_pair_w[NPAIR];

__device__ uint4 g_xh_raw [BB * NN * DD / 8];
__device__ uint4 g_xl_raw [BB * NN * DD / 8];
__device__ uint4 g_xth_raw[BB * DD * NN / 8];
__device__ uint4 g_xtl_raw[BB * DD * NN / 8];

__device__ uint4 g_tw1h_raw[E_TOKN * HNN * NN / 8];
__device__ uint4 g_tw1l_raw[E_TOKN * HNN * NN / 8];
__device__ uint4 g_tw2h_raw[E_TOKN * NN * HNN / 8];
__device__ uint4 g_tw2l_raw[E_TOKN * NN * HNN / 8];
__device__ uint4 g_cw1h_raw[E_CHN * HDD * DD / 8];
__device__ uint4 g_cw1l_raw[E_CHN * HDD * DD / 8];
__device__ uint4 g_cw2h_raw[E_CHN * DD * HDD / 8];
__device__ uint4 g_cw2l_raw[E_CHN * DD * HDD / 8];

__device__ uint4  g_hidh_raw[(size_t)NPAIR * HID_ELEMS / 8];  // ~402 MB
__device__ uint4  g_hidl_raw[(size_t)NPAIR * HID_ELEMS / 8];  // ~402 MB
__device__ float4 g_contrib_raw[(size_t)NPAIR * CON_ELEMS / 4]; // ~201 MB

// Device-code-only accessors
#define g_xh   ((__nv_bfloat16*)g_xh_raw)
#define g_xl   ((__nv_bfloat16*)g_xl_raw)
#define g_xth  ((__nv_bfloat16*)g_xth_raw)
#define g_xtl  ((__nv_bfloat16*)g_xtl_raw)
#define g_tw1h ((__nv_bfloat16*)g_tw1h_raw)
#define g_tw1l ((__nv_bfloat16*)g_tw1l_raw)
#define g_tw2h ((__nv_bfloat16*)g_tw2h_raw)
#define g_tw2l ((__nv_bfloat16*)g_tw2l_raw)
#define g_cw1h ((__nv_bfloat16*)g_cw1h_raw)
#define g_cw1l ((__nv_bfloat16*)g_cw1l_raw)
#define g_cw2h ((__nv_bfloat16*)g_cw2h_raw)
#define g_cw2l ((__nv_bfloat16*)g_cw2l_raw)
#define g_hidh ((__nv_bfloat16*)g_hidh_raw)
#define g_hidl ((__nv_bfloat16*)g_hidl_raw)
#define g_contrib ((float*)g_contrib_raw)

// ---------------------------------------------------------------------------
// Helpers
// ---------------------------------------------------------------------------
__device__ __forceinline__ float gelu_tanh(float v) {
    const float c = 0.7978845608028654f; // sqrt(2/pi)
    float u = c * (v + 0.044715f * v * v * v);
    return 0.5f * v * (1.0f + tanhf(u));
}

// ---------------------------------------------------------------------------
// Kernel: xm[b,d] = mean_n x[b,n,d]
// ---------------------------------------------------------------------------
__global__ void k_mean(const float* __restrict__ x) {
    int idx = blockIdx.x * blockDim.x + threadIdx.x;
    if (idx >= BB * DD) return;
    int b = idx / DD;
    int d = idx - b * DD;
    const float* p = x + (size_t)b * NN * DD + d;
    float s = 0.0f;
    #pragma unroll 8
    for (int n = 0; n < NN; n++) s += p[(size_t)n * DD];
    g_xm[idx] = s * (1.0f / (float)NN);
}

// ---------------------------------------------------------------------------
// Kernel: router logits, softmax, top-2, aux loss. Single block, 256 thr.
// ---------------------------------------------------------------------------
__global__ void k_router(const float* __restrict__ rw, float* __restrict__ out,
                         long long aux_idx, int has_aux) {
    __shared__ float probs[BB][EE];
    __shared__ int   top1s[BB];
    __shared__ float partial[EE];
    int t = threadIdx.x;

    {
        int b = t >> 3, e = t & 7;
        const float* xm = g_xm + b * DD;
        const float* w  = rw + e * DD;
        float s = 0.0f;
        #pragma unroll 8
        for (int d = 0; d < DD; d++) s += xm[d] * w[d];
        probs[b][e] = s;
    }
    __syncthreads();

    if (t < BB) {
        float l[EE];
        float mx = -1e30f;
        #pragma unroll
        for (int e = 0; e < EE; e++) { l[e] = probs[t][e]; mx = fmaxf(mx, l[e]); }
        float sum = 0.0f;
        #pragma unroll
        for (int e = 0; e < EE; e++) { l[e] = expf(l[e] - mx); sum += l[e]; }
        float inv = 1.0f / sum;
        #pragma unroll
        for (int e = 0; e < EE; e++) { l[e] *= inv; probs[t][e] = l[e]; }
        int i0 = 0; float v0 = l[0];
        #pragma unroll
        for (int e = 1; e < EE; e++) if (l[e] > v0) { v0 = l[e]; i0 = e; }
        int i1 = -1; float v1 = -1e30f;
        #pragma unroll
        for (int e = 0; e < EE; e++) if (e != i0 && l[e] > v1) { v1 = l[e]; i1 = e; }
        float inv01 = 1.0f / (v0 + v1);
        g_pair_e[2 * t]     = i0; g_pair_w[2 * t]     = v0 * inv01;
        g_pair_e[2 * t + 1] = i1; g_pair_w[2 * t + 1] = v1 * inv01;
        top1s[t] = i0;
    }
    __syncthreads();

    if (t < EE) {
        float ps = 0.0f; int c = 0;
        for (int b = 0; b < BB; b++) { ps += probs[b][t]; c += (top1s[b] == t); }
        partial[t] = ps * (float)c;
    }
    __syncthreads();

    if (t == 0 && has_aux) {
        float s = 0.0f;
        #pragma unroll
        for (int e = 0; e < EE; e++) s += partial[e];
        out[aux_idx] = s * ((float)EE / ((float)BB * (float)BB));
    }
}

// ---------------------------------------------------------------------------
// Kernel: fp32 -> bf16 hi/lo split. Destination selected by template ID and
// resolved IN DEVICE CODE (never pass device globals from host!).
// DST: 0=x, 1=tok_w1, 2=tok_w2, 3=ch_w1, 4=ch_w2
// ---------------------------------------------------------------------------
template<int DST>
__global__ void k_split(const float* __restrict__ s, int n4) {
    __nv_bfloat16* h;
    __nv_bfloat16* l;
    if      (DST == 0) { h = g_xh;   l = g_xl;   }
    else if (DST == 1) { h = g_tw1h; l = g_tw1l; }
    else if (DST == 2) { h = g_tw2h; l = g_tw2l; }
    else if (DST == 3) { h = g_cw1h; l = g_cw1l; }
    else               { h = g_cw2h; l = g_cw2l; }

    int i = blockIdx.x * 256 + threadIdx.x;
    if (i >= n4) return;
    float4 v = ((const float4*)s)[i];
    __nv_bfloat16 h0 = __float2bfloat16(v.x);
    __nv_bfloat16 h1 = __float2bfloat16(v.y);
    __nv_bfloat16 h2 = __float2bfloat16(v.z);
    __nv_bfloat16 h3 = __float2bfloat16(v.w);
    __nv_bfloat162 hp0; hp0.x = h0; hp0.y = h1;
    __nv_bfloat162 hp1; hp1.x = h2; hp1.y = h3;
    __nv_bfloat162 lp0;
    lp0.x = __float2bfloat16(v.x - __bfloat162float(h0));
    lp0.y = __float2bfloat16(v.y - __bfloat162float(h1));
    __nv_bfloat162 lp1;
    lp1.x = __float2bfloat16(v.z - __bfloat162float(h2));
    lp1.y = __float2bfloat16(v.w - __bfloat162float(h3));
    ((__nv_bfloat162*)h)[i * 2]     = hp0;
    ((__nv_bfloat162*)h)[i * 2 + 1] = hp1;
    ((__nv_bfloat162*)l)[i * 2]     = lp0;
    ((__nv_bfloat162*)l)[i * 2 + 1] = lp1;
}

// ---------------------------------------------------------------------------
// Kernel: x[b][n][d] -> xT hi/lo [b][d][n]  (tiled transpose + split)
// grid (DD/32, NN/32, BB), block (32, 8). Globals referenced in device code.
// ---------------------------------------------------------------------------
__global__ void k_xt_split(const float* __restrict__ x) {
    __shared__ float t[32][33];
    int b  = blockIdx.z;
    int d0 = blockIdx.x * 32;
    int n0 = blockIdx.y * 32;
    int tx = threadIdx.x, ty = threadIdx.y;
    #pragma unroll
    for (int i = 0; i < 4; i++) {
        int n = n0 + ty + i * 8;
        t[ty + i * 8][tx] = x[((size_t)b * NN + n) * DD + d0 + tx];
    }
    __syncthreads();
    #pragma unroll
    for (int i = 0; i < 4; i++) {
        int d = d0 + ty + i * 8;
        float v = t[tx][ty + i * 8];
        __nv_bfloat16 h = __float2bfloat16(v);
        __nv_bfloat16 l = __float2bfloat16(v - __bfloat162float(h));
        size_t o = ((size_t)b * DD + d) * NN + n0 + tx;
        g_xth[o] = h; g_xtl[o] = l;
    }
}

// ---------------------------------------------------------------------------
// WMMA GEMM core: C[m][n] = sum_k A[m][k]*B[n][k],
// split bf16 x3 (hi*hi + hi*lo + lo*hi), fp32 accumulate.
// CTA 128x128, BK=32, 256 threads = 8 warps (2 x 4), warp tile 64x32.
// A tiles stride 48 elems, B tiles 32 elems; 40960B static smem.
// BIAS: 1=per-col(n), 2=per-row(m). SPLIT: write bf16 hi/lo, else fp32.
// ---------------------------------------------------------------------------
#define BK 32
#define ASTR 48
#define BSTR 32

template<int M, int Nn, int K, bool GELU, int BIAS, bool SPLIT>
__device__ void wmma_core(const __nv_bfloat16* Ah, const __nv_bfloat16* Al,
                          const __nv_bfloat16* Bh, const __nv_bfloat16* Bl,
                          const float* __restrict__ bias,
                          float* Cf, __nv_bfloat16* Ch, __nv_bfloat16* Cl) {
    __shared__ __align__(32) unsigned char smraw[2 * 128 * ASTR * 2 + 2 * 128 * BSTR * 2];
    __nv_bfloat16* sAh = (__nv_bfloat16*)smraw;
    __nv_bfloat16* sAl = sAh + 128 * ASTR;
    __nv_bfloat16* sBh = sAl + 128 * ASTR;
    __nv_bfloat16* sBl = sBh + 128 * BSTR;
    float* stage = (float*)smraw;             // reused after main loop

    const int tid = threadIdx.x, lane = tid & 31, wid = tid >> 5;
    const int wm = wid & 1, wn = wid >> 1;    // 2 x 4 warp grid
    const int mT = blockIdx.y * 128, nT = blockIdx.x * 128;

    wmma::fragment<wmma::accumulator, 16, 16, 16, float> acc[4][2];
    #pragma unroll
    for (int mt = 0; mt < 4; mt++)
        #pragma unroll
        for (int p = 0; p < 2; p++) wmma::fill_fragment(acc[mt][p], 0.0f);

    const __nv_bfloat16* pAh = Ah + (size_t)mT * K;
    const __nv_bfloat16* pAl = Al + (size_t)mT * K;
    const __nv_bfloat16* pBh = Bh + (size_t)nT * K;
    const __nv_bfloat16* pBl = Bl + (size_t)nT * K;

    for (int chk = 0; chk < K / BK; chk++) {
        __syncthreads();   // previous iteration's reads done before overwrite
        #pragma unroll
        for (int it = 0; it < 2; it++) {
            int idx = it * 256 + tid;
            int row = idx >> 2, c = idx & 3;
            size_t go = (size_t)row * K + chk * BK + c * 8;
            *(uint4*)&sAh[row * ASTR + c * 8] = *(const uint4*)(pAh + go);
            *(uint4*)&sAl[row * ASTR + c * 8] = *(const uint4*)(pAl + go);
            *(uint4*)&sBh[row * BSTR + c * 8] = *(const uint4*)(pBh + go);
            *(uint4*)&sBl[row * BSTR + c * 8] = *(const uint4*)(pBl + go);
        }
        __syncthreads();

        #pragma unroll
        for (int ks = 0; ks < BK / 16; ks++) {
            wmma::fragment<wmma::matrix_a, 16, 16, 16, __nv_bfloat16, wmma::row_major> af[4], afl[4];
            wmma::fragment<wmma::matrix_b, 16, 16, 16, __nv_bfloat16, wmma::col_major> bf[2], bfl[2];
            #pragma unroll
            for (int mt = 0; mt < 4; mt++)
                wmma::load_matrix_sync(af[mt], &sAh[(wm * 64 + mt * 16) * ASTR + ks * 16], ASTR);
            #pragma unroll
            for (int p = 0; p < 2; p++)
                wmma::load_matrix_sync(bf[p], &sBh[(wn * 32 + p * 16) * BSTR + ks * 16], BSTR);
            // hi * hi
            #pragma unroll
            for (int mt = 0; mt < 4; mt++)
                #pragma unroll
                for (int p = 0; p < 2; p++)
                    wmma::mma_sync(acc[mt][p], af[mt], bf[p], acc[mt][p]);
            // lo * hi
            #pragma unroll
            for (int mt = 0; mt < 4; mt++)
                wmma::load_matrix_sync(afl[mt], &sAl[(wm * 64 + mt * 16) * ASTR + ks * 16], ASTR);
            #pragma unroll
            for (int mt = 0; mt < 4; mt++)
                #pragma unroll
                for (int p = 0; p < 2; p++)
                    wmma::mma_sync(acc[mt][p], afl[mt], bf[p], acc[mt][p]);
            // hi * lo
            #pragma unroll
            for (int p = 0; p < 2; p++)
                wmma::load_matrix_sync(bfl[p], &sBl[(wn * 32 + p * 16) * BSTR + ks * 16], BSTR);
            #pragma unroll
            for (int mt = 0; mt < 4; mt++)
                #pragma unroll
                for (int p = 0; p < 2; p++)
                    wmma::mma_sync(acc[mt][p], af[mt], bfl[p], acc[mt][p]);
        }
    }
    __syncthreads();   // tiles dead; stage reuse is safe

    // --- epilogue via per-warp 16x16 staging (288-float stride: 32B-aligned) ---
    float* st = stage + wid * 288;
    const int r  = lane >> 1;        // 0..15
    const int c0 = (lane & 1) * 8;   // 0 or 8
    #pragma unroll
    for (int mt = 0; mt < 4; mt++) {
        #pragma unroll
        for (int p = 0; p < 2; p++) {
            wmma::store_matrix_sync(st, acc[mt][p], 16, wmma::mem_row_major);
            __syncwarp();
            int row = mT + wm * 64 + mt * 16 + r;
            int col = nT + wn * 32 + p * 16 + c0;
            float v[8];
            #pragma unroll
            for (int j = 0; j < 8; j++) v[j] = st[r * 16 + c0 + j];
            if (BIAS == 1) {
                #pragma unroll
                for (int j = 0; j < 8; j++) v[j] += __ldg(&bias[col + j]);
            } else if (BIAS == 2) {
                float rb = __ldg(&bias[row]);
                #pragma unroll
                for (int j = 0; j < 8; j++) v[j] += rb;
            }
            if (GELU) {
                #pragma unroll
                for (int j = 0; j < 8; j++) v[j] = gelu_tanh(v[j]);
            }
            if (SPLIT) {
                __nv_bfloat162 hv[4], lv[4];
                #pragma unroll
                for (int j = 0; j < 4; j++) {
                    __nv_bfloat16 h0 = __float2bfloat16(v[2 * j]);
                    __nv_bfloat16 h1 = __float2bfloat16(v[2 * j + 1]);
                    hv[j].x = h0; hv[j].y = h1;
                    lv[j].x = __float2bfloat16(v[2 * j]     - __bfloat162float(h0));
                    lv[j].y = __float2bfloat16(v[2 * j + 1] - __bfloat162float(h1));
                }
                *(uint4*)(Ch + (size_t)row * Nn + col) = *(uint4*)hv;
                *(uint4*)(Cl + (size_t)row * Nn + col) = *(uint4*)lv;
            } else {
                *(float4*)(Cf + (size_t)row * Nn + col)     = *(float4*)&v[0];
                *(float4*)(Cf + (size_t)row * Nn + col + 4) = *(float4*)&v[4];
            }
            __syncwarp();
        }
    }
}

// ---------------------------------------------------------------------------
// Expert GEMM wrappers (early exit per pair; all global addresses formed here,
// in device code)
// ---------------------------------------------------------------------------
__global__ void __launch_bounds__(256)
k_tok_l1_tc(const float* __restrict__ b1) {
    int p = blockIdx.z;
    int e = g_pair_e[p];
    if (e >= E_TOKN) return;
    int b = p >> 1;
    // H[p][d][h] = gelu( sum_n xT[b][d][n] * tw1[e][h][n] + b1[e][h] )
    wmma_core<DD, HNN, NN, true, 1, true>(
        g_xth + (size_t)b * DD * NN, g_xtl + (size_t)b * DD * NN,
        g_tw1h + (size_t)e * HNN * NN, g_tw1l + (size_t)e * HNN * NN,
        b1 + e * HNN, nullptr,
        g_hidh + (size_t)p * HID_ELEMS, g_hidl + (size_t)p * HID_ELEMS);
}

__global__ void __launch_bounds__(256)
k_tok_l2_tc(const float* __restrict__ b2) {
    int p = blockIdx.z;
    int e = g_pair_e[p];
    if (e >= E_TOKN) return;
    // contrib[p][n][d] = sum_h tw2[e][n][h] * H[p][d][h] + b2[e][n]
    wmma_core<NN, DD, HNN, false, 2, false>(
        g_tw2h + (size_t)e * NN * HNN, g_tw2l + (size_t)e * NN * HNN,
        g_hidh + (size_t)p * HID_ELEMS, g_hidl + (size_t)p * HID_ELEMS,
        b2 + e * NN,
        g_contrib + (size_t)p * CON_ELEMS, nullptr, nullptr);
}

__global__ void __launch_bounds__(256)
k_ch_l1_tc(const float* __restrict__ b1) {
    int p = blockIdx.z;
    int e = g_pair_e[p];
    if (e < E_TOKN) return;
    e -= E_TOKN;
    int b = p >> 1;
    // G[p][n][h] = gelu( sum_d x[b][n][d] * cw1[e][h][d] + b1[e][h] )
    wmma_core<NN, HDD, DD, true, 1, true>(
        g_xh + (size_t)b * NN * DD, g_xl + (size_t)b * NN * DD,
        g_cw1h + (size_t)e * HDD * DD, g_cw1l + (size_t)e * HDD * DD,
        b1 + e * HDD, nullptr,
        g_hidh + (size_t)p * HID_ELEMS, g_hidl + (size_t)p * HID_ELEMS);
}

__global__ void __launch_bounds__(256)
k_ch_l2_tc(const float* __restrict__ b2) {
    int p = blockIdx.z;
    int e = g_pair_e[p];
    if (e < E_TOKN) return;
    e -= E_TOKN;
    // contrib[p][n][d] = sum_h G[p][n][h] * cw2[e][d][h] + b2[e][d]
    wmma_core<NN, DD, HDD, false, 1, false>(
        g_hidh + (size_t)p * HID_ELEMS, g_hidl + (size_t)p * HID_ELEMS,
        g_cw2h + (size_t)e * DD * HDD, g_cw2l + (size_t)e * DD * HDD,
        b2 + e * DD,
        g_contrib + (size_t)p * CON_ELEMS, nullptr, nullptr);
}

// ---------------------------------------------------------------------------
// Final combine
// ---------------------------------------------------------------------------
__global__ void k_combine(float* __restrict__ out) {
    long long idx = (long long)blockIdx.x * 256 + threadIdx.x;
    if (idx >= (long long)BB * NN * DD) return;
    int b = (int)(idx / (NN * DD));
    int r = (int)(idx - (long long)b * (NN * DD));
    float v0 = g_pair_w[2 * b]     * g_contrib[(size_t)(2 * b) * CON_ELEMS + r];
    float v1 = g_pair_w[2 * b + 1] * g_contrib[(size_t)(2 * b + 1) * CON_ELEMS + r];
    out[idx] = v0 + v1;
}

// ---------------------------------------------------------------------------
// Launch — only harness pointers (d_in/d_out) ever cross host->device.
// ---------------------------------------------------------------------------
extern "C" void kernel_launch(void* const* d_in, const int* in_sizes, int n_in,
                              void* d_out, int out_size) {
    const float* x        = (const float*)d_in[0];
    const float* router_w = (const float*)d_in[1];
    const float* tok_w1   = (const float*)d_in[2];
    const float* tok_b1   = (const float*)d_in[3];
    const float* tok_w2   = (const float*)d_in[4];
    const float* tok_b2   = (const float*)d_in[5];
    const float* ch_w1    = (const float*)d_in[6];
    const float* ch_b1    = (const float*)d_in[7];
    const float* ch_w2    = (const float*)d_in[8];
    const float* ch_b2    = (const float*)d_in[9];
    float* out = (float*)d_out;

    long long bnd = (long long)BB * NN * DD;
    int has_aux = (long long)out_size > bnd;

    k_mean<<<(BB * DD + 255) / 256, 256>>>(x);
    k_router<<<1, 256>>>(router_w, out, bnd, has_aux);

    // Conversions (fp32 -> bf16 hi/lo); destinations resolved device-side
    {
        int n;
        n = BB * NN * DD / 4;
        k_split<0><<<(n + 255) / 256, 256>>>(x, n);
        dim3 g(DD / 32, NN / 32, BB);
        k_xt_split<<<g, dim3(32, 8)>>>(x);
        n = E_TOKN * HNN * NN / 4;
        k_split<1><<<(n + 255) / 256, 256>>>(tok_w1, n);
        n = E_TOKN * NN * HNN / 4;
        k_split<2><<<(n + 255) / 256, 256>>>(tok_w2, n);
        n = E_CHN * HDD * DD / 4;
        k_split<3><<<(n + 255) / 256, 256>>>(ch_w1, n);
        n = E_CHN * DD * HDD / 4;
        k_split<4><<<(n + 255) / 256, 256>>>(ch_w2, n);
    }

    // Expert GEMMs (WMMA tensor path)
    dim3 g_tok1(HNN / 128, DD / 128, NPAIR);   // 32 x 6 x 64
    k_tok_l1_tc<<<g_tok1, 256>>>(tok_b1);

    dim3 g_ch1(HDD / 128, NN / 128, NPAIR);    // 24 x 8 x 64
    k_ch_l1_tc<<<g_ch1, 256>>>(ch_b1);

    dim3 g_l2(DD / 128, NN / 128, NPAIR);      // 6 x 8 x 64
    k_tok_l2_tc<<<g_l2, 256>>>(tok_b2);
    k_ch_l2_tc<<<g_l2, 256>>>(ch_b2);

    k_combine<<<(unsigned)((bnd + 255) / 256), 256>>>(out);
}

// round 7
// speedup vs baseline: 2.0415x; 1.3368x over previous
#include <cuda_runtime.h>
#include <cuda_bf16.h>
#include <mma.h>
#include <math.h>
#include <stdint.h>

using namespace nvcuda;

// ---------------------------------------------------------------------------
// Problem constants
// ---------------------------------------------------------------------------
#define BB 32
#define NN 1024
#define DD 768
#define E_TOKN 4
#define E_CHN 4
#define EE 8
#define TOPK 2
#define HNN 4096
#define HDD 3072
#define NPAIR (BB * TOPK)            // 64 selected (batch, expert) pairs
#define HID_ELEMS (DD * HNN)         // 3145728 == NN*HDD
#define CON_ELEMS (NN * DD)          // 786432

// ---------------------------------------------------------------------------
// Static device scratch — uint4/float4-typed for 16B alignment.
// RULE (root cause of rounds 3-5): device-global addresses must ONLY be formed
// in DEVICE code; host-side g_* is the shadow symbol (ATS makes it writable!).
// ---------------------------------------------------------------------------
__device__ float g_xm[BB * DD];
__device__ int   g_pair_e[NPAIR];
__device__ float g_pair_w[NPAIR];

__device__ uint4 g_xh_raw [BB * NN * DD / 8];
__device__ uint4 g_xl_raw [BB * NN * DD / 8];
__device__ uint4 g_xth_raw[BB * DD * NN / 8];
__device__ uint4 g_xtl_raw[BB * DD * NN / 8];

__device__ uint4 g_tw1h_raw[E_TOKN * HNN * NN / 8];
__device__ uint4 g_tw1l_raw[E_TOKN * HNN * NN / 8];
__device__ uint4 g_tw2h_raw[E_TOKN * NN * HNN / 8];
__device__ uint4 g_tw2l_raw[E_TOKN * NN * HNN / 8];
__device__ uint4 g_cw1h_raw[E_CHN * HDD * DD / 8];
__device__ uint4 g_cw1l_raw[E_CHN * HDD * DD / 8];
__device__ uint4 g_cw2h_raw[E_CHN * DD * HDD / 8];
__device__ uint4 g_cw2l_raw[E_CHN * DD * HDD / 8];

__device__ uint4  g_hidh_raw[(size_t)NPAIR * HID_ELEMS / 8];
__device__ uint4  g_hidl_raw[(size_t)NPAIR * HID_ELEMS / 8];
__device__ float4 g_contrib_raw[(size_t)NPAIR * CON_ELEMS / 4];

#define g_xh   ((__nv_bfloat16*)g_xh_raw)
#define g_xl   ((__nv_bfloat16*)g_xl_raw)
#define g_xth  ((__nv_bfloat16*)g_xth_raw)
#define g_xtl  ((__nv_bfloat16*)g_xtl_raw)
#define g_tw1h ((__nv_bfloat16*)g_tw1h_raw)
#define g_tw1l ((__nv_bfloat16*)g_tw1l_raw)
#define g_tw2h ((__nv_bfloat16*)g_tw2h_raw)
#define g_tw2l ((__nv_bfloat16*)g_tw2l_raw)
#define g_cw1h ((__nv_bfloat16*)g_cw1h_raw)
#define g_cw1l ((__nv_bfloat16*)g_cw1l_raw)
#define g_cw2h ((__nv_bfloat16*)g_cw2h_raw)
#define g_cw2l ((__nv_bfloat16*)g_cw2l_raw)
#define g_hidh ((__nv_bfloat16*)g_hidh_raw)
#define g_hidl ((__nv_bfloat16*)g_hidl_raw)
#define g_contrib ((float*)g_contrib_raw)

// ---------------------------------------------------------------------------
// Helpers
// ---------------------------------------------------------------------------
__device__ __forceinline__ float gelu_tanh(float v) {
    const float c = 0.7978845608028654f; // sqrt(2/pi)
    float u = c * (v + 0.044715f * v * v * v);
    return 0.5f * v * (1.0f + tanhf(u));
}

__device__ __forceinline__ uint32_t smem_u32(const void* p) {
    uint32_t a;
    asm("{ .reg .u64 t; cvta.to.shared.u64 t, %1; cvt.u32.u64 %0, t; }"
        : "=r"(a) : "l"(p));
    return a;
}

#define CP_ASYNC16(dst32, src) \
    asm volatile("cp.async.cg.shared.global [%0], [%1], 16;" \
                 :: "r"(dst32), "l"(src) : "memory")
#define CP_COMMIT()  asm volatile("cp.async.commit_group;" ::: "memory")
#define CP_WAIT0()   asm volatile("cp.async.wait_group 0;" ::: "memory")
#define CP_WAIT1()   asm volatile("cp.async.wait_group 1;" ::: "memory")

// ---------------------------------------------------------------------------
// Kernel: xm[b,d] = mean_n x[b,n,d]
// ---------------------------------------------------------------------------
__global__ void k_mean(const float* __restrict__ x) {
    int idx = blockIdx.x * blockDim.x + threadIdx.x;
    if (idx >= BB * DD) return;
    int b = idx / DD;
    int d = idx - b * DD;
    const float* p = x + (size_t)b * NN * DD + d;
    float s = 0.0f;
    #pragma unroll 8
    for (int n = 0; n < NN; n++) s += p[(size_t)n * DD];
    g_xm[idx] = s * (1.0f / (float)NN);
}

// ---------------------------------------------------------------------------
// Kernel: router logits, softmax, top-2, aux loss. Single block, 256 thr.
// ---------------------------------------------------------------------------
__global__ void k_router(const float* __restrict__ rw, float* __restrict__ out,
                         long long aux_idx, int has_aux) {
    __shared__ float probs[BB][EE];
    __shared__ int   top1s[BB];
    __shared__ float partial[EE];
    int t = threadIdx.x;

    {
        int b = t >> 3, e = t & 7;
        const float* xm = g_xm + b * DD;
        const float* w  = rw + e * DD;
        float s = 0.0f;
        #pragma unroll 8
        for (int d = 0; d < DD; d++) s += xm[d] * w[d];
        probs[b][e] = s;
    }
    __syncthreads();

    if (t < BB) {
        float l[EE];
        float mx = -1e30f;
        #pragma unroll
        for (int e = 0; e < EE; e++) { l[e] = probs[t][e]; mx = fmaxf(mx, l[e]); }
        float sum = 0.0f;
        #pragma unroll
        for (int e = 0; e < EE; e++) { l[e] = expf(l[e] - mx); sum += l[e]; }
        float inv = 1.0f / sum;
        #pragma unroll
        for (int e = 0; e < EE; e++) { l[e] *= inv; probs[t][e] = l[e]; }
        int i0 = 0; float v0 = l[0];
        #pragma unroll
        for (int e = 1; e < EE; e++) if (l[e] > v0) { v0 = l[e]; i0 = e; }
        int i1 = -1; float v1 = -1e30f;
        #pragma unroll
        for (int e = 0; e < EE; e++) if (e != i0 && l[e] > v1) { v1 = l[e]; i1 = e; }
        float inv01 = 1.0f / (v0 + v1);
        g_pair_e[2 * t]     = i0; g_pair_w[2 * t]     = v0 * inv01;
        g_pair_e[2 * t + 1] = i1; g_pair_w[2 * t + 1] = v1 * inv01;
        top1s[t] = i0;
    }
    __syncthreads();

    if (t < EE) {
        float ps = 0.0f; int c = 0;
        for (int b = 0; b < BB; b++) { ps += probs[b][t]; c += (top1s[b] == t); }
        partial[t] = ps * (float)c;
    }
    __syncthreads();

    if (t == 0 && has_aux) {
        float s = 0.0f;
        #pragma unroll
        for (int e = 0; e < EE; e++) s += partial[e];
        out[aux_idx] = s * ((float)EE / ((float)BB * (float)BB));
    }
}

// ---------------------------------------------------------------------------
// Kernel: fp32 -> bf16 hi/lo split; destination resolved in device code.
// DST: 0=x, 1=tok_w1, 2=tok_w2, 3=ch_w1, 4=ch_w2
// ---------------------------------------------------------------------------
template<int DST>
__global__ void k_split(const float* __restrict__ s, int n4) {
    __nv_bfloat16* h;
    __nv_bfloat16* l;
    if      (DST == 0) { h = g_xh;   l = g_xl;   }
    else if (DST == 1) { h = g_tw1h; l = g_tw1l; }
    else if (DST == 2) { h = g_tw2h; l = g_tw2l; }
    else if (DST == 3) { h = g_cw1h; l = g_cw1l; }
    else               { h = g_cw2h; l = g_cw2l; }

    int i = blockIdx.x * 256 + threadIdx.x;
    if (i >= n4) return;
    float4 v = ((const float4*)s)[i];
    __nv_bfloat16 h0 = __float2bfloat16(v.x);
    __nv_bfloat16 h1 = __float2bfloat16(v.y);
    __nv_bfloat16 h2 = __float2bfloat16(v.z);
    __nv_bfloat16 h3 = __float2bfloat16(v.w);
    __nv_bfloat162 hp0; hp0.x = h0; hp0.y = h1;
    __nv_bfloat162 hp1; hp1.x = h2; hp1.y = h3;
    __nv_bfloat162 lp0;
    lp0.x = __float2bfloat16(v.x - __bfloat162float(h0));
    lp0.y = __float2bfloat16(v.y - __bfloat162float(h1));
    __nv_bfloat162 lp1;
    lp1.x = __float2bfloat16(v.z - __bfloat162float(h2));
    lp1.y = __float2bfloat16(v.w - __bfloat162float(h3));
    ((__nv_bfloat162*)h)[i * 2]     = hp0;
    ((__nv_bfloat162*)h)[i * 2 + 1] = hp1;
    ((__nv_bfloat162*)l)[i * 2]     = lp0;
    ((__nv_bfloat162*)l)[i * 2 + 1] = lp1;
}

// ---------------------------------------------------------------------------
// Kernel: x[b][n][d] -> xT hi/lo [b][d][n]  (tiled transpose + split)
// ---------------------------------------------------------------------------
__global__ void k_xt_split(const float* __restrict__ x) {
    __shared__ float t[32][33];
    int b  = blockIdx.z;
    int d0 = blockIdx.x * 32;
    int n0 = blockIdx.y * 32;
    int tx = threadIdx.x, ty = threadIdx.y;
    #pragma unroll
    for (int i = 0; i < 4; i++) {
        int n = n0 + ty + i * 8;
        t[ty + i * 8][tx] = x[((size_t)b * NN + n) * DD + d0 + tx];
    }
    __syncthreads();
    #pragma unroll
    for (int i = 0; i < 4; i++) {
        int d = d0 + ty + i * 8;
        float v = t[tx][ty + i * 8];
        __nv_bfloat16 h = __float2bfloat16(v);
        __nv_bfloat16 l = __float2bfloat16(v - __bfloat162float(h));
        size_t o = ((size_t)b * DD + d) * NN + n0 + tx;
        g_xth[o] = h; g_xtl[o] = l;
    }
}

// ---------------------------------------------------------------------------
// WMMA GEMM core, cp.async 2-stage double buffered.
//   C[m][n] = sum_k A[m][k]*B[n][k], split bf16 x3, fp32 accumulate.
// CTA 128x128, BK=32, 256 threads = 8 warps (2 x 4), warp tile 64x32.
// Tiles: 128 rows x 40-elem stride (80B rows, cp.async-aligned,
// conflict-free ldmatrix phases). Stage = 4 tiles = 40960B; 2 stages dynamic.
// BIAS: 1=per-col(n), 2=per-row(m). SPLIT: write bf16 hi/lo, else fp32.
// ---------------------------------------------------------------------------
#define BK 32
#define STRD 40
#define TILE_B (128 * STRD * 2)    // 10240
#define STAGE_B (4 * TILE_B)       // 40960
#define SMEM_TOT (2 * STAGE_B)     // 81920

template<int M, int Nn, int K, bool GELU, int BIAS, bool SPLIT>
__device__ void wmma_core(const __nv_bfloat16* Ah, const __nv_bfloat16* Al,
                          const __nv_bfloat16* Bh, const __nv_bfloat16* Bl,
                          const float* __restrict__ bias,
                          float* Cf, __nv_bfloat16* Ch, __nv_bfloat16* Cl) {
    extern __shared__ __align__(128) unsigned char dsm[];
    const uint32_t sbase = smem_u32(dsm);

    const int tid = threadIdx.x, lane = tid & 31, wid = tid >> 5;
    const int wm = wid & 1, wn = wid >> 1;    // 2 x 4 warp grid
    const int mT = blockIdx.y * 128, nT = blockIdx.x * 128;

    wmma::fragment<wmma::accumulator, 16, 16, 16, float> acc[4][2];
    #pragma unroll
    for (int mt = 0; mt < 4; mt++)
        #pragma unroll
        for (int p = 0; p < 2; p++) wmma::fill_fragment(acc[mt][p], 0.0f);

    const __nv_bfloat16* src[4] = {
        Ah + (size_t)mT * K, Al + (size_t)mT * K,
        Bh + (size_t)nT * K, Bl + (size_t)nT * K };

    // Per-thread copy coords: 512 x 16B chunks per tile, 2 per thread per tile.
    const int crow0 = tid >> 2, cc = tid & 3;            // rows 0..63
    const int crow1 = crow0 + 64;                        // rows 64..127

    auto load_stage = [&](int stage, int chk) {
        uint32_t sb = sbase + stage * STAGE_B;
        #pragma unroll
        for (int tI = 0; tI < 4; tI++) {
            const __nv_bfloat16* g = src[tI] + (size_t)chk * BK + cc * 8;
            uint32_t db = sb + tI * TILE_B + cc * 16;
            CP_ASYNC16(db + crow0 * (STRD * 2), g + (size_t)crow0 * K);
            CP_ASYNC16(db + crow1 * (STRD * 2), g + (size_t)crow1 * K);
        }
        CP_COMMIT();
    };

    const int NCH = K / BK;
    load_stage(0, 0);

    for (int chk = 0; chk < NCH; chk++) {
        if (chk + 1 < NCH) {
            load_stage((chk + 1) & 1, chk + 1);
            CP_WAIT1();
        } else {
            CP_WAIT0();
        }
        __syncthreads();

        unsigned char* st = dsm + (chk & 1) * STAGE_B;
        __nv_bfloat16* sAh = (__nv_bfloat16*)(st);
        __nv_bfloat16* sAl = (__nv_bfloat16*)(st + TILE_B);
        __nv_bfloat16* sBh = (__nv_bfloat16*)(st + 2 * TILE_B);
        __nv_bfloat16* sBl = (__nv_bfloat16*)(st + 3 * TILE_B);

        #pragma unroll
        for (int ks = 0; ks < BK / 16; ks++) {
            wmma::fragment<wmma::matrix_a, 16, 16, 16, __nv_bfloat16, wmma::row_major> af[4], afl[4];
            wmma::fragment<wmma::matrix_b, 16, 16, 16, __nv_bfloat16, wmma::col_major> bf[2], bfl[2];
            #pragma unroll
            for (int mt = 0; mt < 4; mt++)
                wmma::load_matrix_sync(af[mt], &sAh[(wm * 64 + mt * 16) * STRD + ks * 16], STRD);
            #pragma unroll
            for (int p = 0; p < 2; p++)
                wmma::load_matrix_sync(bf[p], &sBh[(wn * 32 + p * 16) * STRD + ks * 16], STRD);
            // hi * hi
            #pragma unroll
            for (int mt = 0; mt < 4; mt++)
                #pragma unroll
                for (int p = 0; p < 2; p++)
                    wmma::mma_sync(acc[mt][p], af[mt], bf[p], acc[mt][p]);
            // lo * hi
            #pragma unroll
            for (int mt = 0; mt < 4; mt++)
                wmma::load_matrix_sync(afl[mt], &sAl[(wm * 64 + mt * 16) * STRD + ks * 16], STRD);
            #pragma unroll
            for (int mt = 0; mt < 4; mt++)
                #pragma unroll
                for (int p = 0; p < 2; p++)
                    wmma::mma_sync(acc[mt][p], afl[mt], bf[p], acc[mt][p]);
            // hi * lo
            #pragma unroll
            for (int p = 0; p < 2; p++)
                wmma::load_matrix_sync(bfl[p], &sBl[(wn * 32 + p * 16) * STRD + ks * 16], STRD);
            #pragma unroll
            for (int mt = 0; mt < 4; mt++)
                #pragma unroll
                for (int p = 0; p < 2; p++)
                    wmma::mma_sync(acc[mt][p], af[mt], bfl[p], acc[mt][p]);
        }
        __syncthreads();
    }

    // --- epilogue via per-warp 16x16 staging (smem reuse; 288-float stride) ---
    float* stage = (float*)dsm;
    float* st = stage + wid * 288;
    const int r  = lane >> 1;        // 0..15
    const int c0 = (lane & 1) * 8;   // 0 or 8
    #pragma unroll
    for (int mt = 0; mt < 4; mt++) {
        #pragma unroll
        for (int p = 0; p < 2; p++) {
            wmma::store_matrix_sync(st, acc[mt][p], 16, wmma::mem_row_major);
            __syncwarp();
            int row = mT + wm * 64 + mt * 16 + r;
            int col = nT + wn * 32 + p * 16 + c0;
            float v[8];
            #pragma unroll
            for (int j = 0; j < 8; j++) v[j] = st[r * 16 + c0 + j];
            if (BIAS == 1) {
                #pragma unroll
                for (int j = 0; j < 8; j++) v[j] += __ldg(&bias[col + j]);
            } else if (BIAS == 2) {
                float rb = __ldg(&bias[row]);
                #pragma unroll
                for (int j = 0; j < 8; j++) v[j] += rb;
            }
            if (GELU) {
                #pragma unroll
                for (int j = 0; j < 8; j++) v[j] = gelu_tanh(v[j]);
            }
            if (SPLIT) {
                __nv_bfloat162 hv[4], lv[4];
                #pragma unroll
                for (int j = 0; j < 4; j++) {
                    __nv_bfloat16 h0 = __float2bfloat16(v[2 * j]);
                    __nv_bfloat16 h1 = __float2bfloat16(v[2 * j + 1]);
                    hv[j].x = h0; hv[j].y = h1;
                    lv[j].x = __float2bfloat16(v[2 * j]     - __bfloat162float(h0));
                    lv[j].y = __float2bfloat16(v[2 * j + 1] - __bfloat162float(h1));
                }
                *(uint4*)(Ch + (size_t)row * Nn + col) = *(uint4*)hv;
                *(uint4*)(Cl + (size_t)row * Nn + col) = *(uint4*)lv;
            } else {
                *(float4*)(Cf + (size_t)row * Nn + col)     = *(float4*)&v[0];
                *(float4*)(Cf + (size_t)row * Nn + col + 4) = *(float4*)&v[4];
            }
            __syncwarp();
        }
    }
}

// ---------------------------------------------------------------------------
// Expert GEMM wrappers (early exit per pair; globals resolved in device code)
// ---------------------------------------------------------------------------
__global__ void __launch_bounds__(256)
k_tok_l1_tc(const float* __restrict__ b1) {
    int p = blockIdx.z;
    int e = g_pair_e[p];
    if (e >= E_TOKN) return;
    int b = p >> 1;
    wmma_core<DD, HNN, NN, true, 1, true>(
        g_xth + (size_t)b * DD * NN, g_xtl + (size_t)b * DD * NN,
        g_tw1h + (size_t)e * HNN * NN, g_tw1l + (size_t)e * HNN * NN,
        b1 + e * HNN, nullptr,
        g_hidh + (size_t)p * HID_ELEMS, g_hidl + (size_t)p * HID_ELEMS);
}

__global__ void __launch_bounds__(256)
k_tok_l2_tc(const float* __restrict__ b2) {
    int p = blockIdx.z;
    int e = g_pair_e[p];
    if (e >= E_TOKN) return;
    wmma_core<NN, DD, HNN, false, 2, false>(
        g_tw2h + (size_t)e * NN * HNN, g_tw2l + (size_t)e * NN * HNN,
        g_hidh + (size_t)p * HID_ELEMS, g_hidl + (size_t)p * HID_ELEMS,
        b2 + e * NN,
        g_contrib + (size_t)p * CON_ELEMS, nullptr, nullptr);
}

__global__ void __launch_bounds__(256)
k_ch_l1_tc(const float* __restrict__ b1) {
    int p = blockIdx.z;
    int e = g_pair_e[p];
    if (e < E_TOKN) return;
    e -= E_TOKN;
    int b = p >> 1;
    wmma_core<NN, HDD, DD, true, 1, true>(
        g_xh + (size_t)b * NN * DD, g_xl + (size_t)b * NN * DD,
        g_cw1h + (size_t)e * HDD * DD, g_cw1l + (size_t)e * HDD * DD,
        b1 + e * HDD, nullptr,
        g_hidh + (size_t)p * HID_ELEMS, g_hidl + (size_t)p * HID_ELEMS);
}

__global__ void __launch_bounds__(256)
k_ch_l2_tc(const float* __restrict__ b2) {
    int p = blockIdx.z;
    int e = g_pair_e[p];
    if (e < E_TOKN) return;
    e -= E_TOKN;
    wmma_core<NN, DD, HDD, false, 1, false>(
        g_hidh + (size_t)p * HID_ELEMS, g_hidl + (size_t)p * HID_ELEMS,
        g_cw2h + (size_t)e * DD * HDD, g_cw2l + (size_t)e * DD * HDD,
        b2 + e * DD,
        g_contrib + (size_t)p * CON_ELEMS, nullptr, nullptr);
}

// ---------------------------------------------------------------------------
// Final combine
// ---------------------------------------------------------------------------
__global__ void k_combine(float* __restrict__ out) {
    long long idx = (long long)blockIdx.x * 256 + threadIdx.x;
    if (idx >= (long long)BB * NN * DD) return;
    int b = (int)(idx / (NN * DD));
    int r = (int)(idx - (long long)b * (NN * DD));
    float v0 = g_pair_w[2 * b]     * g_contrib[(size_t)(2 * b) * CON_ELEMS + r];
    float v1 = g_pair_w[2 * b + 1] * g_contrib[(size_t)(2 * b + 1) * CON_ELEMS + r];
    out[idx] = v0 + v1;
}

// ---------------------------------------------------------------------------
// Launch — only harness pointers cross host->device. Launch order puts
// k_tok_l1_tc at index 5 so ncu's fixed "-s 5 -c 1" captures a GEMM kernel.
// ---------------------------------------------------------------------------
extern "C" void kernel_launch(void* const* d_in, const int* in_sizes, int n_in,
                              void* d_out, int out_size) {
    const float* x        = (const float*)d_in[0];
    const float* router_w = (const float*)d_in[1];
    const float* tok_w1   = (const float*)d_in[2];
    const float* tok_b1   = (const float*)d_in[3];
    const float* tok_w2   = (const float*)d_in[4];
    const float* tok_b2   = (const float*)d_in[5];
    const float* ch_w1    = (const float*)d_in[6];
    const float* ch_b1    = (const float*)d_in[7];
    const float* ch_w2    = (const float*)d_in[8];
    const float* ch_b2    = (const float*)d_in[9];
    float* out = (float*)d_out;

    long long bnd = (long long)BB * NN * DD;
    int has_aux = (long long)out_size > bnd;

    cudaFuncSetAttribute(k_tok_l1_tc, cudaFuncAttributeMaxDynamicSharedMemorySize, SMEM_TOT);
    cudaFuncSetAttribute(k_tok_l2_tc, cudaFuncAttributeMaxDynamicSharedMemorySize, SMEM_TOT);
    cudaFuncSetAttribute(k_ch_l1_tc,  cudaFuncAttributeMaxDynamicSharedMemorySize, SMEM_TOT);
    cudaFuncSetAttribute(k_ch_l2_tc,  cudaFuncAttributeMaxDynamicSharedMemorySize, SMEM_TOT);

    // 0: mean, 1: router
    k_mean<<<(BB * DD + 255) / 256, 256>>>(x);
    k_router<<<1, 256>>>(router_w, out, bnd, has_aux);

    // 2: x split, 3: xT split, 4: tok_w1 split
    int n = BB * NN * DD / 4;
    k_split<0><<<(n + 255) / 256, 256>>>(x, n);
    dim3 gx(DD / 32, NN / 32, BB);
    k_xt_split<<<gx, dim3(32, 8)>>>(x);
    n = E_TOKN * HNN * NN / 4;
    k_split<1><<<(n + 255) / 256, 256>>>(tok_w1, n);

    // 5: token L1 GEMM  <-- ncu capture lands here
    dim3 g_tok1(HNN / 128, DD / 128, NPAIR);   // 32 x 6 x 64
    k_tok_l1_tc<<<g_tok1, 256, SMEM_TOT>>>(tok_b1);

    // 6: ch_w1 split, 7: channel L1 GEMM
    n = E_CHN * HDD * DD / 4;
    k_split<3><<<(n + 255) / 256, 256>>>(ch_w1, n);
    dim3 g_ch1(HDD / 128, NN / 128, NPAIR);    // 24 x 8 x 64
    k_ch_l1_tc<<<g_ch1, 256, SMEM_TOT>>>(ch_b1);

    // 8-9: remaining weight splits
    n = E_TOKN * NN * HNN / 4;
    k_split<2><<<(n + 255) / 256, 256>>>(tok_w2, n);
    n = E_CHN * DD * HDD / 4;
    k_split<4><<<(n + 255) / 256, 256>>>(ch_w2, n);

    // 10-11: L2 GEMMs
    dim3 g_l2(DD / 128, NN / 128, NPAIR);      // 6 x 8 x 64
    k_tok_l2_tc<<<g_l2, 256, SMEM_TOT>>>(tok_b2);
    k_ch_l2_tc<<<g_l2, 256, SMEM_TOT>>>(ch_b2);

    // 12: combine
    k_combine<<<(unsigned)((bnd + 255) / 256), 256>>>(out);
}

// round 8
// speedup vs baseline: 6.0021x; 2.9401x over previous
#include <cuda_runtime.h>
#include <cuda_fp16.h>
#include <mma.h>
#include <math.h>
#include <stdint.h>

using namespace nvcuda;

// ---------------------------------------------------------------------------
// Problem constants
// ---------------------------------------------------------------------------
#define BB 32
#define NN 1024
#define DD 768
#define E_TOKN 4
#define E_CHN 4
#define EE 8
#define TOPK 2
#define HNN 4096
#define HDD 3072
#define NPAIR (BB * TOPK)            // 64 selected (batch, expert) pairs
#define HID_ELEMS (DD * HNN)         // 3145728 == NN*HDD
#define CON_ELEMS (NN * DD)          // 786432

// ---------------------------------------------------------------------------
// Static device scratch (uint4-typed: guaranteed 16B alignment).
// RULE (rounds 3-5 root cause): device-global addresses are formed ONLY in
// device code — host-side g_* is the shadow symbol (ATS makes it writable!).
// ---------------------------------------------------------------------------
__device__ float g_xm[BB * DD];
__device__ int   g_pair_e[NPAIR];
__device__ float g_pair_w[NPAIR];

__device__ uint4 g_xf_raw  [BB * NN * DD / 8];          // x fp16 [b][n][d]
__device__ uint4 g_xtf_raw [BB * DD * NN / 8];          // x^T fp16 [b][d][n]
__device__ uint4 g_tw1f_raw[E_TOKN * HNN * NN / 8];
__device__ uint4 g_tw2f_raw[E_TOKN * NN * HNN / 8];
__device__ uint4 g_cw1f_raw[E_CHN * HDD * DD / 8];
__device__ uint4 g_cw2f_raw[E_CHN * DD * HDD / 8];
__device__ uint4 g_hidf_raw[(size_t)NPAIR * HID_ELEMS / 8];   // ~402 MB fp16
__device__ float4 g_contrib_raw[(size_t)NPAIR * CON_ELEMS / 4]; // ~201 MB

#define g_xf   ((__half*)g_xf_raw)
#define g_xtf  ((__half*)g_xtf_raw)
#define g_tw1f ((__half*)g_tw1f_raw)
#define g_tw2f ((__half*)g_tw2f_raw)
#define g_cw1f ((__half*)g_cw1f_raw)
#define g_cw2f ((__half*)g_cw2f_raw)
#define g_hidf ((__half*)g_hidf_raw)
#define g_contrib ((float*)g_contrib_raw)

// ---------------------------------------------------------------------------
// Helpers
// ---------------------------------------------------------------------------
__device__ __forceinline__ float gelu_tanh(float v) {
    const float c = 0.7978845608028654f; // sqrt(2/pi)
    float u = c * (v + 0.044715f * v * v * v);
    return 0.5f * v * (1.0f + tanhf(u));
}

__device__ __forceinline__ uint32_t smem_u32(const void* p) {
    uint32_t a;
    asm("{ .reg .u64 t; cvta.to.shared.u64 t, %1; cvt.u32.u64 %0, t; }"
        : "=r"(a) : "l"(p));
    return a;
}

#define CP_ASYNC16(dst32, src) \
    asm volatile("cp.async.cg.shared.global [%0], [%1], 16;" \
                 :: "r"(dst32), "l"(src) : "memory")
#define CP_COMMIT()  asm volatile("cp.async.commit_group;" ::: "memory")
#define CP_WAIT0()   asm volatile("cp.async.wait_group 0;" ::: "memory")
#define CP_WAIT1()   asm volatile("cp.async.wait_group 1;" ::: "memory")

// ---------------------------------------------------------------------------
// Kernel: xm[b,d] = mean_n x[b,n,d]
// ---------------------------------------------------------------------------
__global__ void k_mean(const float* __restrict__ x) {
    int idx = blockIdx.x * blockDim.x + threadIdx.x;
    if (idx >= BB * DD) return;
    int b = idx / DD;
    int d = idx - b * DD;
    const float* p = x + (size_t)b * NN * DD + d;
    float s = 0.0f;
    #pragma unroll 8
    for (int n = 0; n < NN; n++) s += p[(size_t)n * DD];
    g_xm[idx] = s * (1.0f / (float)NN);
}

// ---------------------------------------------------------------------------
// Kernel: router logits, softmax, top-2, aux loss. Single block, 256 thr.
// ---------------------------------------------------------------------------
__global__ void k_router(const float* __restrict__ rw, float* __restrict__ out,
                         long long aux_idx, int has_aux) {
    __shared__ float probs[BB][EE];
    __shared__ int   top1s[BB];
    __shared__ float partial[EE];
    int t = threadIdx.x;

    {
        int b = t >> 3, e = t & 7;
        const float* xm = g_xm + b * DD;
        const float* w  = rw + e * DD;
        float s = 0.0f;
        #pragma unroll 8
        for (int d = 0; d < DD; d++) s += xm[d] * w[d];
        probs[b][e] = s;
    }
    __syncthreads();

    if (t < BB) {
        float l[EE];
        float mx = -1e30f;
        #pragma unroll
        for (int e = 0; e < EE; e++) { l[e] = probs[t][e]; mx = fmaxf(mx, l[e]); }
        float sum = 0.0f;
        #pragma unroll
        for (int e = 0; e < EE; e++) { l[e] = expf(l[e] - mx); sum += l[e]; }
        float inv = 1.0f / sum;
        #pragma unroll
        for (int e = 0; e < EE; e++) { l[e] *= inv; probs[t][e] = l[e]; }
        int i0 = 0; float v0 = l[0];
        #pragma unroll
        for (int e = 1; e < EE; e++) if (l[e] > v0) { v0 = l[e]; i0 = e; }
        int i1 = -1; float v1 = -1e30f;
        #pragma unroll
        for (int e = 0; e < EE; e++) if (e != i0 && l[e] > v1) { v1 = l[e]; i1 = e; }
        float inv01 = 1.0f / (v0 + v1);
        g_pair_e[2 * t]     = i0; g_pair_w[2 * t]     = v0 * inv01;
        g_pair_e[2 * t + 1] = i1; g_pair_w[2 * t + 1] = v1 * inv01;
        top1s[t] = i0;
    }
    __syncthreads();

    if (t < EE) {
        float ps = 0.0f; int c = 0;
        for (int b = 0; b < BB; b++) { ps += probs[b][t]; c += (top1s[b] == t); }
        partial[t] = ps * (float)c;
    }
    __syncthreads();

    if (t == 0 && has_aux) {
        float s = 0.0f;
        #pragma unroll
        for (int e = 0; e < EE; e++) s += partial[e];
        out[aux_idx] = s * ((float)EE / ((float)BB * (float)BB));
    }
}

// ---------------------------------------------------------------------------
// Fused conversion kernel: all fp32 -> fp16 conversions + x transpose in ONE
// launch. Block regions selected by blockIdx.x; destinations resolved in
// device code. Region sizes (blocks of 256 thr, 1024 floats each):
// ---------------------------------------------------------------------------
#define NB_X   24576   // x elementwise
#define NB_XT  24576   // x transpose (24 x 32 x 32 tiles)
#define NB_TW1 16384
#define NB_TW2 16384
#define NB_CW1 9216
#define NB_CW2 9216
#define NB_TOTAL (NB_X + NB_XT + NB_TW1 + NB_TW2 + NB_CW1 + NB_CW2)

__device__ __forceinline__ void cvt4(const float* __restrict__ s, __half* d, int i) {
    float4 v = ((const float4*)s)[i];
    __half2 a = __floats2half2_rn(v.x, v.y);
    __half2 b = __floats2half2_rn(v.z, v.w);
    uint2 u;
    u.x = *reinterpret_cast<uint32_t*>(&a);
    u.y = *reinterpret_cast<uint32_t*>(&b);
    ((uint2*)d)[i] = u;
}

__global__ void k_convert(const float* __restrict__ x,
                          const float* __restrict__ tw1,
                          const float* __restrict__ tw2,
                          const float* __restrict__ cw1,
                          const float* __restrict__ cw2) {
    __shared__ float t[32][33];
    int bid = blockIdx.x;
    int tid = threadIdx.x;

    if (bid < NB_X) {
        cvt4(x, g_xf, bid * 256 + tid);
    } else if (bid < NB_X + NB_XT) {
        int r = bid - NB_X;
        int b = r / 768;                 // 768 = (DD/32)*(NN/32)
        int rem = r - b * 768;
        int nblk = rem / 24;             // 24 = DD/32
        int dblk = rem - nblk * 24;
        int d0 = dblk * 32, n0 = nblk * 32;
        int tx = tid & 31, ty = tid >> 5;    // 32 x 8
        #pragma unroll
        for (int i = 0; i < 4; i++) {
            int n = n0 + ty + i * 8;
            t[ty + i * 8][tx] = x[((size_t)b * NN + n) * DD + d0 + tx];
        }
        __syncthreads();
        #pragma unroll
        for (int i = 0; i < 4; i++) {
            int d = d0 + ty + i * 8;
            g_xtf[((size_t)b * DD + d) * NN + n0 + tx] =
                __float2half_rn(t[tx][ty + i * 8]);
        }
    } else if (bid < NB_X + NB_XT + NB_TW1) {
        cvt4(tw1, g_tw1f, (bid - NB_X - NB_XT) * 256 + tid);
    } else if (bid < NB_X + NB_XT + NB_TW1 + NB_TW2) {
        cvt4(tw2, g_tw2f, (bid - NB_X - NB_XT - NB_TW1) * 256 + tid);
    } else if (bid < NB_X + NB_XT + NB_TW1 + NB_TW2 + NB_CW1) {
        cvt4(cw1, g_cw1f, (bid - NB_X - NB_XT - NB_TW1 - NB_TW2) * 256 + tid);
    } else {
        cvt4(cw2, g_cw2f, (bid - NB_X - NB_XT - NB_TW1 - NB_TW2 - NB_CW1) * 256 + tid);
    }
}

// ---------------------------------------------------------------------------
// WMMA fp16 GEMM core, single-term, cp.async 2-stage double buffered.
//   C[m][n] = sum_k A[m][k]*B[n][k], fp16 operands, fp32 accumulate.
// CTA 128x256, BK=64, 256 threads = 8 warps (2 x 4), warp tile 64x64.
// Tiles: rows of 64 halves padded to 72 (144B stride: 16B-aligned for
// cp.async; 144/4 mod 32 = 4 -> conflict-free ldmatrix phases).
// BIAS: 1=per-col(n), 2=per-row(m). TOHALF: write fp16, else fp32.
// ---------------------------------------------------------------------------
#define BK 64
#define RSTR 144                      // bytes per smem row
#define STRDH 72                      // halves per smem row
#define A_TILE_B (128 * RSTR)         // 18432
#define B_TILE_B (256 * RSTR)         // 36864
#define STAGE_B (A_TILE_B + B_TILE_B) // 55296
#define SMEM_TOT (2 * STAGE_B)        // 110592

template<int M, int Nn, int K, bool GELU, int BIAS, bool TOHALF>
__device__ void wmma_core(const __half* A, const __half* B,
                          const float* __restrict__ bias,
                          float* Cf, __half* Ch) {
    extern __shared__ __align__(128) unsigned char dsm[];
    const uint32_t sbase = smem_u32(dsm);

    const int tid = threadIdx.x, lane = tid & 31, wid = tid >> 5;
    const int wm = wid & 1, wn = wid >> 1;    // 2 x 4 warp grid, 64x64 tiles
    const int mT = blockIdx.y * 128, nT = blockIdx.x * 256;

    wmma::fragment<wmma::accumulator, 16, 16, 16, float> acc[4][4];
    #pragma unroll
    for (int mt = 0; mt < 4; mt++)
        #pragma unroll
        for (int p = 0; p < 4; p++) wmma::fill_fragment(acc[mt][p], 0.0f);

    const __half* pA = A + (size_t)mT * K;
    const __half* pB = B + (size_t)nT * K;

    auto load_stage = [&](int stage, int chk) {
        uint32_t sb = sbase + stage * STAGE_B;
        #pragma unroll
        for (int it = 0; it < 4; it++) {           // A: 1024 16B chunks
            int idx = it * 256 + tid;
            int row = idx >> 3, c = idx & 7;
            CP_ASYNC16(sb + row * RSTR + c * 16,
                       pA + (size_t)row * K + chk * BK + c * 8);
        }
        #pragma unroll
        for (int it = 0; it < 8; it++) {           // B: 2048 16B chunks
            int idx = it * 256 + tid;
            int row = idx >> 3, c = idx & 7;
            CP_ASYNC16(sb + A_TILE_B + row * RSTR + c * 16,
                       pB + (size_t)row * K + chk * BK + c * 8);
        }
        CP_COMMIT();
    };

    const int NCH = K / BK;
    load_stage(0, 0);

    for (int chk = 0; chk < NCH; chk++) {
        if (chk + 1 < NCH) {
            load_stage((chk + 1) & 1, chk + 1);
            CP_WAIT1();
        } else {
            CP_WAIT0();
        }
        __syncthreads();

        __half* sA = (__half*)(dsm + (chk & 1) * STAGE_B);
        __half* sB = (__half*)(dsm + (chk & 1) * STAGE_B + A_TILE_B);

        #pragma unroll
        for (int ks = 0; ks < BK / 16; ks++) {
            wmma::fragment<wmma::matrix_a, 16, 16, 16, __half, wmma::row_major> af[4];
            wmma::fragment<wmma::matrix_b, 16, 16, 16, __half, wmma::col_major> bf[4];
            #pragma unroll
            for (int mt = 0; mt < 4; mt++)
                wmma::load_matrix_sync(af[mt], &sA[(wm * 64 + mt * 16) * STRDH + ks * 16], STRDH);
            #pragma unroll
            for (int p = 0; p < 4; p++)
                wmma::load_matrix_sync(bf[p], &sB[(wn * 64 + p * 16) * STRDH + ks * 16], STRDH);
            #pragma unroll
            for (int mt = 0; mt < 4; mt++)
                #pragma unroll
                for (int p = 0; p < 4; p++)
                    wmma::mma_sync(acc[mt][p], af[mt], bf[p], acc[mt][p]);
        }
        __syncthreads();
    }

    // --- epilogue via per-warp 16x16 fp32 staging (smem reuse) ---
    float* st = (float*)dsm + wid * 288;
    const int r  = lane >> 1;        // 0..15
    const int c0 = (lane & 1) * 8;   // 0 or 8
    #pragma unroll
    for (int mt = 0; mt < 4; mt++) {
        #pragma unroll
        for (int p = 0; p < 4; p++) {
            wmma::store_matrix_sync(st, acc[mt][p], 16, wmma::mem_row_major);
            __syncwarp();
            int row = mT + wm * 64 + mt * 16 + r;
            int col = nT + wn * 64 + p * 16 + c0;
            float v[8];
            #pragma unroll
            for (int j = 0; j < 8; j++) v[j] = st[r * 16 + c0 + j];
            if (BIAS == 1) {
                #pragma unroll
                for (int j = 0; j < 8; j++) v[j] += __ldg(&bias[col + j]);
            } else if (BIAS == 2) {
                float rb = __ldg(&bias[row]);
                #pragma unroll
                for (int j = 0; j < 8; j++) v[j] += rb;
            }
            if (GELU) {
                #pragma unroll
                for (int j = 0; j < 8; j++) v[j] = gelu_tanh(v[j]);
            }
            if (TOHALF) {
                __half2 hv[4];
                #pragma unroll
                for (int j = 0; j < 4; j++)
                    hv[j] = __floats2half2_rn(v[2 * j], v[2 * j + 1]);
                *(uint4*)(Ch + (size_t)row * Nn + col) = *(uint4*)hv;
            } else {
                *(float4*)(Cf + (size_t)row * Nn + col)     = *(float4*)&v[0];
                *(float4*)(Cf + (size_t)row * Nn + col + 4) = *(float4*)&v[4];
            }
            __syncwarp();
        }
    }
}

// ---------------------------------------------------------------------------
// Expert GEMM wrappers (early exit per pair; globals resolved in device code)
// ---------------------------------------------------------------------------
__global__ void __launch_bounds__(256)
k_tok_l1_tc(const float* __restrict__ b1) {
    int p = blockIdx.z;
    int e = g_pair_e[p];
    if (e >= E_TOKN) return;
    int b = p >> 1;
    // H[p][d][h] = gelu( sum_n xT[b][d][n] * tw1[e][h][n] + b1[e][h] )
    wmma_core<DD, HNN, NN, true, 1, true>(
        g_xtf + (size_t)b * DD * NN,
        g_tw1f + (size_t)e * HNN * NN,
        b1 + e * HNN,
        nullptr, g_hidf + (size_t)p * HID_ELEMS);
}

__global__ void __launch_bounds__(256)
k_tok_l2_tc(const float* __restrict__ b2) {
    int p = blockIdx.z;
    int e = g_pair_e[p];
    if (e >= E_TOKN) return;
    // contrib[p][n][d] = sum_h tw2[e][n][h] * H[p][d][h] + b2[e][n]
    wmma_core<NN, DD, HNN, false, 2, false>(
        g_tw2f + (size_t)e * NN * HNN,
        g_hidf + (size_t)p * HID_ELEMS,
        b2 + e * NN,
        g_contrib + (size_t)p * CON_ELEMS, nullptr);
}

__global__ void __launch_bounds__(256)
k_ch_l1_tc(const float* __restrict__ b1) {
    int p = blockIdx.z;
    int e = g_pair_e[p];
    if (e < E_TOKN) return;
    e -= E_TOKN;
    int b = p >> 1;
    // G[p][n][h] = gelu( sum_d x[b][n][d] * cw1[e][h][d] + b1[e][h] )
    wmma_core<NN, HDD, DD, true, 1, true>(
        g_xf + (size_t)b * NN * DD,
        g_cw1f + (size_t)e * HDD * DD,
        b1 + e * HDD,
        nullptr, g_hidf + (size_t)p * HID_ELEMS);
}

__global__ void __launch_bounds__(256)
k_ch_l2_tc(const float* __restrict__ b2) {
    int p = blockIdx.z;
    int e = g_pair_e[p];
    if (e < E_TOKN) return;
    e -= E_TOKN;
    // contrib[p][n][d] = sum_h G[p][n][h] * cw2[e][d][h] + b2[e][d]
    wmma_core<NN, DD, HDD, false, 1, false>(
        g_hidf + (size_t)p * HID_ELEMS,
        g_cw2f + (size_t)e * DD * HDD,
        b2 + e * DD,
        g_contrib + (size_t)p * CON_ELEMS, nullptr);
}

// ---------------------------------------------------------------------------
// Final combine
// ---------------------------------------------------------------------------
__global__ void k_combine(float* __restrict__ out) {
    long long idx = (long long)blockIdx.x * 256 + threadIdx.x;
    if (idx >= (long long)BB * NN * DD) return;
    int b = (int)(idx / (NN * DD));
    int r = (int)(idx - (long long)b * (NN * DD));
    float v0 = g_pair_w[2 * b]     * g_contrib[(size_t)(2 * b) * CON_ELEMS + r];
    float v1 = g_pair_w[2 * b + 1] * g_contrib[(size_t)(2 * b + 1) * CON_ELEMS + r];
    out[idx] = v0 + v1;
}

// ---------------------------------------------------------------------------
// Launch — only harness pointers cross host->device. Observed ncu capture
// lands on launch index 3 -> that is k_tok_l1_tc here.
// ---------------------------------------------------------------------------
extern "C" void kernel_launch(void* const* d_in, const int* in_sizes, int n_in,
                              void* d_out, int out_size) {
    const float* x        = (const float*)d_in[0];
    const float* router_w = (const float*)d_in[1];
    const float* tok_w1   = (const float*)d_in[2];
    const float* tok_b1   = (const float*)d_in[3];
    const float* tok_w2   = (const float*)d_in[4];
    const float* tok_b2   = (const float*)d_in[5];
    const float* ch_w1    = (const float*)d_in[6];
    const float* ch_b1    = (const float*)d_in[7];
    const float* ch_w2    = (const float*)d_in[8];
    const float* ch_b2    = (const float*)d_in[9];
    float* out = (float*)d_out;

    long long bnd = (long long)BB * NN * DD;
    int has_aux = (long long)out_size > bnd;

    cudaFuncSetAttribute(k_tok_l1_tc, cudaFuncAttributeMaxDynamicSharedMemorySize, SMEM_TOT);
    cudaFuncSetAttribute(k_tok_l2_tc, cudaFuncAttributeMaxDynamicSharedMemorySize, SMEM_TOT);
    cudaFuncSetAttribute(k_ch_l1_tc,  cudaFuncAttributeMaxDynamicSharedMemorySize, SMEM_TOT);
    cudaFuncSetAttribute(k_ch_l2_tc,  cudaFuncAttributeMaxDynamicSharedMemorySize, SMEM_TOT);

    // 0: mean, 1: router, 2: fused conversions
    k_mean<<<(BB * DD + 255) / 256, 256>>>(x);
    k_router<<<1, 256>>>(router_w, out, bnd, has_aux);
    k_convert<<<NB_TOTAL, 256>>>(x, tok_w1, tok_w2, ch_w1, ch_w2);

    // 3: token L1 GEMM  <-- ncu capture target
    dim3 g_tok1(HNN / 256, DD / 128, NPAIR);   // 16 x 6 x 64
    k_tok_l1_tc<<<g_tok1, 256, SMEM_TOT>>>(tok_b1);

    // 4: channel L1 GEMM
    dim3 g_ch1(HDD / 256, NN / 128, NPAIR);    // 12 x 8 x 64
    k_ch_l1_tc<<<g_ch1, 256, SMEM_TOT>>>(ch_b1);

    // 5-6: L2 GEMMs
    dim3 g_l2(DD / 256, NN / 128, NPAIR);      // 3 x 8 x 64
    k_tok_l2_tc<<<g_l2, 256, SMEM_TOT>>>(tok_b2);
    k_ch_l2_tc<<<g_l2, 256, SMEM_TOT>>>(ch_b2);

    // 7: combine
    k_combine<<<(unsigned)((bnd + 255) / 256), 256>>>(out);
}

// round 9
// speedup vs baseline: 7.1997x; 1.1995x over previous
#include <cuda_runtime.h>
#include <cuda_fp16.h>
#include <mma.h>
#include <math.h>
#include <stdint.h>

using namespace nvcuda;

// ---------------------------------------------------------------------------
// Problem constants
// ---------------------------------------------------------------------------
#define BB 32
#define NN 1024
#define DD 768
#define E_TOKN 4
#define E_CHN 4
#define EE 8
#define TOPK 2
#define HNN 4096
#define HDD 3072
#define NPAIR (BB * TOPK)            // 64 selected (batch, expert) pairs
#define HID_ELEMS (DD * HNN)         // 3145728 == NN*HDD
#define CON_ELEMS (NN * DD)          // 786432

// ---------------------------------------------------------------------------
// Static device scratch (uint4-typed: guaranteed 16B alignment).
// RULE (rounds 3-5 root cause): device-global addresses are formed ONLY in
// device code — host-side g_* is the shadow symbol (ATS makes it writable!).
// ---------------------------------------------------------------------------
__device__ float g_xm[BB * DD];
__device__ int   g_pair_e[NPAIR];
__device__ float g_pair_w[NPAIR];

__device__ uint4 g_xf_raw  [BB * NN * DD / 8];          // x fp16 [b][n][d]
__device__ uint4 g_xtf_raw [BB * DD * NN / 8];          // x^T fp16 [b][d][n]
__device__ uint4 g_tw1f_raw[E_TOKN * HNN * NN / 8];
__device__ uint4 g_tw2f_raw[E_TOKN * NN * HNN / 8];
__device__ uint4 g_cw1f_raw[E_CHN * HDD * DD / 8];
__device__ uint4 g_cw2f_raw[E_CHN * DD * HDD / 8];
__device__ uint4 g_hidf_raw[(size_t)NPAIR * HID_ELEMS / 8];   // ~402 MB fp16
__device__ float4 g_contrib_raw[(size_t)NPAIR * CON_ELEMS / 4]; // ~201 MB

#define g_xf   ((__half*)g_xf_raw)
#define g_xtf  ((__half*)g_xtf_raw)
#define g_tw1f ((__half*)g_tw1f_raw)
#define g_tw2f ((__half*)g_tw2f_raw)
#define g_cw1f ((__half*)g_cw1f_raw)
#define g_cw2f ((__half*)g_cw2f_raw)
#define g_hidf ((__half*)g_hidf_raw)
#define g_contrib ((float*)g_contrib_raw)

// ---------------------------------------------------------------------------
// Helpers
// ---------------------------------------------------------------------------
__device__ __forceinline__ float gelu_tanh(float v) {
    const float c = 0.7978845608028654f; // sqrt(2/pi)
    float u = c * (v + 0.044715f * v * v * v);
    return 0.5f * v * (1.0f + tanhf(u));
}

__device__ __forceinline__ uint32_t smem_u32(const void* p) {
    uint32_t a;
    asm("{ .reg .u64 t; cvta.to.shared.u64 t, %1; cvt.u32.u64 %0, t; }"
        : "=r"(a) : "l"(p));
    return a;
}

#define CP_ASYNC16(dst32, src) \
    asm volatile("cp.async.cg.shared.global [%0], [%1], 16;" \
                 :: "r"(dst32), "l"(src) : "memory")
#define CP_COMMIT()  asm volatile("cp.async.commit_group;" ::: "memory")
#define CP_WAIT0()   asm volatile("cp.async.wait_group 0;" ::: "memory")
#define CP_WAIT1()   asm volatile("cp.async.wait_group 1;" ::: "memory")

// ---------------------------------------------------------------------------
// Kernel: xm[b,d] = mean_n x[b,n,d]
// ---------------------------------------------------------------------------
__global__ void k_mean(const float* __restrict__ x) {
    int idx = blockIdx.x * blockDim.x + threadIdx.x;
    if (idx >= BB * DD) return;
    int b = idx / DD;
    int d = idx - b * DD;
    const float* p = x + (size_t)b * NN * DD + d;
    float s = 0.0f;
    #pragma unroll 8
    for (int n = 0; n < NN; n++) s += p[(size_t)n * DD];
    g_xm[idx] = s * (1.0f / (float)NN);
}

// ---------------------------------------------------------------------------
// Kernel: router logits, softmax, top-2, aux loss. Single block, 256 thr.
// ---------------------------------------------------------------------------
__global__ void k_router(const float* __restrict__ rw, float* __restrict__ out,
                         long long aux_idx, int has_aux) {
    __shared__ float probs[BB][EE];
    __shared__ int   top1s[BB];
    __shared__ float partial[EE];
    int t = threadIdx.x;

    {
        int b = t >> 3, e = t & 7;
        const float* xm = g_xm + b * DD;
        const float* w  = rw + e * DD;
        float s = 0.0f;
        #pragma unroll 8
        for (int d = 0; d < DD; d++) s += xm[d] * w[d];
        probs[b][e] = s;
    }
    __syncthreads();

    if (t < BB) {
        float l[EE];
        float mx = -1e30f;
        #pragma unroll
        for (int e = 0; e < EE; e++) { l[e] = probs[t][e]; mx = fmaxf(mx, l[e]); }
        float sum = 0.0f;
        #pragma unroll
        for (int e = 0; e < EE; e++) { l[e] = expf(l[e] - mx); sum += l[e]; }
        float inv = 1.0f / sum;
        #pragma unroll
        for (int e = 0; e < EE; e++) { l[e] *= inv; probs[t][e] = l[e]; }
        int i0 = 0; float v0 = l[0];
        #pragma unroll
        for (int e = 1; e < EE; e++) if (l[e] > v0) { v0 = l[e]; i0 = e; }
        int i1 = -1; float v1 = -1e30f;
        #pragma unroll
        for (int e = 0; e < EE; e++) if (e != i0 && l[e] > v1) { v1 = l[e]; i1 = e; }
        float inv01 = 1.0f / (v0 + v1);
        g_pair_e[2 * t]     = i0; g_pair_w[2 * t]     = v0 * inv01;
        g_pair_e[2 * t + 1] = i1; g_pair_w[2 * t + 1] = v1 * inv01;
        top1s[t] = i0;
    }
    __syncthreads();

    if (t < EE) {
        float ps = 0.0f; int c = 0;
        for (int b = 0; b < BB; b++) { ps += probs[b][t]; c += (top1s[b] == t); }
        partial[t] = ps * (float)c;
    }
    __syncthreads();

    if (t == 0 && has_aux) {
        float s = 0.0f;
        #pragma unroll
        for (int e = 0; e < EE; e++) s += partial[e];
        out[aux_idx] = s * ((float)EE / ((float)BB * (float)BB));
    }
}

// ---------------------------------------------------------------------------
// Fused conversion kernel: all fp32 -> fp16 conversions + x transpose.
// Regions by blockIdx.x; destinations resolved in device code.
// ---------------------------------------------------------------------------
#define NB_X   24576
#define NB_XT  24576
#define NB_TW1 16384
#define NB_TW2 16384
#define NB_CW1 9216
#define NB_CW2 9216
#define NB_TOTAL (NB_X + NB_XT + NB_TW1 + NB_TW2 + NB_CW1 + NB_CW2)

__device__ __forceinline__ void cvt4(const float* __restrict__ s, __half* d, int i) {
    float4 v = ((const float4*)s)[i];
    __half2 a = __floats2half2_rn(v.x, v.y);
    __half2 b = __floats2half2_rn(v.z, v.w);
    uint2 u;
    u.x = *reinterpret_cast<uint32_t*>(&a);
    u.y = *reinterpret_cast<uint32_t*>(&b);
    ((uint2*)d)[i] = u;
}

__global__ void k_convert(const float* __restrict__ x,
                          const float* __restrict__ tw1,
                          const float* __restrict__ tw2,
                          const float* __restrict__ cw1,
                          const float* __restrict__ cw2) {
    __shared__ float t[32][33];
    int bid = blockIdx.x;
    int tid = threadIdx.x;

    if (bid < NB_X) {
        cvt4(x, g_xf, bid * 256 + tid);
    } else if (bid < NB_X + NB_XT) {
        int r = bid - NB_X;
        int b = r / 768;
        int rem = r - b * 768;
        int nblk = rem / 24;
        int dblk = rem - nblk * 24;
        int d0 = dblk * 32, n0 = nblk * 32;
        int tx = tid & 31, ty = tid >> 5;
        #pragma unroll
        for (int i = 0; i < 4; i++) {
            int n = n0 + ty + i * 8;
            t[ty + i * 8][tx] = x[((size_t)b * NN + n) * DD + d0 + tx];
        }
        __syncthreads();
        #pragma unroll
        for (int i = 0; i < 4; i++) {
            int d = d0 + ty + i * 8;
            g_xtf[((size_t)b * DD + d) * NN + n0 + tx] =
                __float2half_rn(t[tx][ty + i * 8]);
        }
    } else if (bid < NB_X + NB_XT + NB_TW1) {
        cvt4(tw1, g_tw1f, (bid - NB_X - NB_XT) * 256 + tid);
    } else if (bid < NB_X + NB_XT + NB_TW1 + NB_TW2) {
        cvt4(tw2, g_tw2f, (bid - NB_X - NB_XT - NB_TW1) * 256 + tid);
    } else if (bid < NB_X + NB_XT + NB_TW1 + NB_TW2 + NB_CW1) {
        cvt4(cw1, g_cw1f, (bid - NB_X - NB_XT - NB_TW1 - NB_TW2) * 256 + tid);
    } else {
        cvt4(cw2, g_cw2f, (bid - NB_X - NB_XT - NB_TW1 - NB_TW2 - NB_CW1) * 256 + tid);
    }
}

// ---------------------------------------------------------------------------
// WMMA fp16 GEMM core, cp.async 2-stage, occupancy-tuned.
//   C[m][n] = sum_k A[m][k]*B[n][k], fp16 operands, fp32 accumulate.
// CTA 128x128, 128 threads = 4 warps (2x2), warp tile 64x64, BK=64.
// smem/stage = 256 rows x 144B = 36864 B; 2 stages = 73728 B -> 2-3 CTAs/SM
// (vs 1 before): cross-CTA overlap hides syncthreads + ldmatrix latency.
// BIAS: 1=per-col(n), 2=per-row(m). TOHALF: write fp16, else fp32.
// ---------------------------------------------------------------------------
#define BK 64
#define RSTR 144                      // bytes per smem row
#define STRDH 72                      // halves per smem row
#define A_TILE_B (128 * RSTR)         // 18432
#define STAGE_B (2 * A_TILE_B)        // 36864 (A rows + B rows)
#define SMEM_TOT (2 * STAGE_B)        // 73728

template<int M, int Nn, int K, bool GELU, int BIAS, bool TOHALF>
__device__ void wmma_core(const __half* A, const __half* B,
                          const float* __restrict__ bias,
                          float* Cf, __half* Ch) {
    extern __shared__ __align__(128) unsigned char dsm[];
    const uint32_t sbase = smem_u32(dsm);

    const int tid = threadIdx.x, lane = tid & 31, wid = tid >> 5;
    const int wm = wid & 1, wn = wid >> 1;    // 2 x 2 warp grid, 64x64 tiles
    const int mT = blockIdx.y * 128, nT = blockIdx.x * 128;

    wmma::fragment<wmma::accumulator, 16, 16, 16, float> acc[4][4];
    #pragma unroll
    for (int mt = 0; mt < 4; mt++)
        #pragma unroll
        for (int p = 0; p < 4; p++) wmma::fill_fragment(acc[mt][p], 0.0f);

    const __half* pA = A + (size_t)mT * K;
    const __half* pB = B + (size_t)nT * K;

    // Per stage: A 128 rows + B 128 rows, 8 x 16B chunks per row = 2048 chunks,
    // 16 per thread.
    auto load_stage = [&](int stage, int chk) {
        uint32_t sb = sbase + stage * STAGE_B;
        #pragma unroll
        for (int it = 0; it < 8; it++) {           // A
            int idx = it * 128 + tid;
            int row = idx >> 3, c = idx & 7;
            CP_ASYNC16(sb + row * RSTR + c * 16,
                       pA + (size_t)row * K + chk * BK + c * 8);
        }
        #pragma unroll
        for (int it = 0; it < 8; it++) {           // B
            int idx = it * 128 + tid;
            int row = idx >> 3, c = idx & 7;
            CP_ASYNC16(sb + A_TILE_B + row * RSTR + c * 16,
                       pB + (size_t)row * K + chk * BK + c * 8);
        }
        CP_COMMIT();
    };

    const int NCH = K / BK;
    load_stage(0, 0);

    for (int chk = 0; chk < NCH; chk++) {
        if (chk + 1 < NCH) {
            load_stage((chk + 1) & 1, chk + 1);
            CP_WAIT1();
        } else {
            CP_WAIT0();
        }
        __syncthreads();

        __half* sA = (__half*)(dsm + (chk & 1) * STAGE_B);
        __half* sB = (__half*)(dsm + (chk & 1) * STAGE_B + A_TILE_B);

        #pragma unroll
        for (int ks = 0; ks < BK / 16; ks++) {
            wmma::fragment<wmma::matrix_a, 16, 16, 16, __half, wmma::row_major> af[4];
            wmma::fragment<wmma::matrix_b, 16, 16, 16, __half, wmma::col_major> bf[4];
            #pragma unroll
            for (int mt = 0; mt < 4; mt++)
                wmma::load_matrix_sync(af[mt], &sA[(wm * 64 + mt * 16) * STRDH + ks * 16], STRDH);
            #pragma unroll
            for (int p = 0; p < 4; p++)
                wmma::load_matrix_sync(bf[p], &sB[(wn * 64 + p * 16) * STRDH + ks * 16], STRDH);
            #pragma unroll
            for (int mt = 0; mt < 4; mt++)
                #pragma unroll
                for (int p = 0; p < 4; p++)
                    wmma::mma_sync(acc[mt][p], af[mt], bf[p], acc[mt][p]);
        }
        __syncthreads();
    }

    // --- epilogue via per-warp 16x16 fp32 staging (smem reuse) ---
    float* st = (float*)dsm + wid * 288;
    const int r  = lane >> 1;        // 0..15
    const int c0 = (lane & 1) * 8;   // 0 or 8
    #pragma unroll
    for (int mt = 0; mt < 4; mt++) {
        #pragma unroll
        for (int p = 0; p < 4; p++) {
            wmma::store_matrix_sync(st, acc[mt][p], 16, wmma::mem_row_major);
            __syncwarp();
            int row = mT + wm * 64 + mt * 16 + r;
            int col = nT + wn * 64 + p * 16 + c0;
            float v[8];
            #pragma unroll
            for (int j = 0; j < 8; j++) v[j] = st[r * 16 + c0 + j];
            if (BIAS == 1) {
                #pragma unroll
                for (int j = 0; j < 8; j++) v[j] += __ldg(&bias[col + j]);
            } else if (BIAS == 2) {
                float rb = __ldg(&bias[row]);
                #pragma unroll
                for (int j = 0; j < 8; j++) v[j] += rb;
            }
            if (GELU) {
                #pragma unroll
                for (int j = 0; j < 8; j++) v[j] = gelu_tanh(v[j]);
            }
            if (TOHALF) {
                __half2 hv[4];
                #pragma unroll
                for (int j = 0; j < 4; j++)
                    hv[j] = __floats2half2_rn(v[2 * j], v[2 * j + 1]);
                *(uint4*)(Ch + (size_t)row * Nn + col) = *(uint4*)hv;
            } else {
                *(float4*)(Cf + (size_t)row * Nn + col)     = *(float4*)&v[0];
                *(float4*)(Cf + (size_t)row * Nn + col + 4) = *(float4*)&v[4];
            }
            __syncwarp();
        }
    }
}

// ---------------------------------------------------------------------------
// Expert GEMM wrappers (early exit per pair; globals resolved in device code)
// ---------------------------------------------------------------------------
__global__ void __launch_bounds__(128, 3)
k_tok_l1_tc(const float* __restrict__ b1) {
    int p = blockIdx.z;
    int e = g_pair_e[p];
    if (e >= E_TOKN) return;
    int b = p >> 1;
    // H[p][d][h] = gelu( sum_n xT[b][d][n] * tw1[e][h][n] + b1[e][h] )
    wmma_core<DD, HNN, NN, true, 1, true>(
        g_xtf + (size_t)b * DD * NN,
        g_tw1f + (size_t)e * HNN * NN,
        b1 + e * HNN,
        nullptr, g_hidf + (size_t)p * HID_ELEMS);
}

__global__ void __launch_bounds__(128, 3)
k_tok_l2_tc(const float* __restrict__ b2) {
    int p = blockIdx.z;
    int e = g_pair_e[p];
    if (e >= E_TOKN) return;
    // contrib[p][n][d] = sum_h tw2[e][n][h] * H[p][d][h] + b2[e][n]
    wmma_core<NN, DD, HNN, false, 2, false>(
        g_tw2f + (size_t)e * NN * HNN,
        g_hidf + (size_t)p * HID_ELEMS,
        b2 + e * NN,
        g_contrib + (size_t)p * CON_ELEMS, nullptr);
}

__global__ void __launch_bounds__(128, 3)
k_ch_l1_tc(const float* __restrict__ b1) {
    int p = blockIdx.z;
    int e = g_pair_e[p];
    if (e < E_TOKN) return;
    e -= E_TOKN;
    int b = p >> 1;
    // G[p][n][h] = gelu( sum_d x[b][n][d] * cw1[e][h][d] + b1[e][h] )
    wmma_core<NN, HDD, DD, true, 1, true>(
        g_xf + (size_t)b * NN * DD,
        g_cw1f + (size_t)e * HDD * DD,
        b1 + e * HDD,
        nullptr, g_hidf + (size_t)p * HID_ELEMS);
}

__global__ void __launch_bounds__(128, 3)
k_ch_l2_tc(const float* __restrict__ b2) {
    int p = blockIdx.z;
    int e = g_pair_e[p];
    if (e < E_TOKN) return;
    e -= E_TOKN;
    // contrib[p][n][d] = sum_h G[p][n][h] * cw2[e][d][h] + b2[e][d]
    wmma_core<NN, DD, HDD, false, 1, false>(
        g_hidf + (size_t)p * HID_ELEMS,
        g_cw2f + (size_t)e * DD * HDD,
        b2 + e * DD,
        g_contrib + (size_t)p * CON_ELEMS, nullptr);
}

// ---------------------------------------------------------------------------
// Final combine
// ---------------------------------------------------------------------------
__global__ void k_combine(float* __restrict__ out) {
    long long idx = (long long)blockIdx.x * 256 + threadIdx.x;
    if (idx >= (long long)BB * NN * DD) return;
    int b = (int)(idx / (NN * DD));
    int r = (int)(idx - (long long)b * (NN * DD));
    float v0 = g_pair_w[2 * b]     * g_contrib[(size_t)(2 * b) * CON_ELEMS + r];
    float v1 = g_pair_w[2 * b + 1] * g_contrib[(size_t)(2 * b + 1) * CON_ELEMS + r];
    out[idx] = v0 + v1;
}

// ---------------------------------------------------------------------------
// Launch — only harness pointers cross host->device. ncu capture lands on
// launch index 3 = k_tok_l1_tc.
// ---------------------------------------------------------------------------
extern "C" void kernel_launch(void* const* d_in, const int* in_sizes, int n_in,
                              void* d_out, int out_size) {
    const float* x        = (const float*)d_in[0];
    const float* router_w = (const float*)d_in[1];
    const float* tok_w1   = (const float*)d_in[2];
    const float* tok_b1   = (const float*)d_in[3];
    const float* tok_w2   = (const float*)d_in[4];
    const float* tok_b2   = (const float*)d_in[5];
    const float* ch_w1    = (const float*)d_in[6];
    const float* ch_b1    = (const float*)d_in[7];
    const float* ch_w2    = (const float*)d_in[8];
    const float* ch_b2    = (const float*)d_in[9];
    float* out = (float*)d_out;

    long long bnd = (long long)BB * NN * DD;
    int has_aux = (long long)out_size > bnd;

    cudaFuncSetAttribute(k_tok_l1_tc, cudaFuncAttributeMaxDynamicSharedMemorySize, SMEM_TOT);
    cudaFuncSetAttribute(k_tok_l2_tc, cudaFuncAttributeMaxDynamicSharedMemorySize, SMEM_TOT);
    cudaFuncSetAttribute(k_ch_l1_tc,  cudaFuncAttributeMaxDynamicSharedMemorySize, SMEM_TOT);
    cudaFuncSetAttribute(k_ch_l2_tc,  cudaFuncAttributeMaxDynamicSharedMemorySize, SMEM_TOT);

    // 0: mean, 1: router, 2: fused conversions
    k_mean<<<(BB * DD + 255) / 256, 256>>>(x);
    k_router<<<1, 256>>>(router_w, out, bnd, has_aux);
    k_convert<<<NB_TOTAL, 256>>>(x, tok_w1, tok_w2, ch_w1, ch_w2);

    // 3: token L1 GEMM  <-- ncu capture target
    dim3 g_tok1(HNN / 128, DD / 128, NPAIR);   // 32 x 6 x 64
    k_tok_l1_tc<<<g_tok1, 128, SMEM_TOT>>>(tok_b1);

    // 4: channel L1 GEMM
    dim3 g_ch1(HDD / 128, NN / 128, NPAIR);    // 24 x 8 x 64
    k_ch_l1_tc<<<g_ch1, 128, SMEM_TOT>>>(ch_b1);

    // 5-6: L2 GEMMs
    dim3 g_l2(DD / 128, NN / 128, NPAIR);      // 6 x 8 x 64
    k_tok_l2_tc<<<g_l2, 128, SMEM_TOT>>>(tok_b2);
    k_ch_l2_tc<<<g_l2, 128, SMEM_TOT>>>(ch_b2);

    // 7: combine
    k_combine<<<(unsigned)((bnd + 255) / 256), 256>>>(out);
}